// round 1
// baseline (speedup 1.0000x reference)
#include <cuda_runtime.h>

#define BB 8
#define NPTS 2048
#define KNN 20
#define NG 8
#define EPSV 1e-5f

#define NEG_INF __int_as_float(0xff800000)

// ---------------- device scratch (static: no allocation allowed) ----------------
__device__ float g_pd[BB][NPTS][NPTS];     // pairwise "negative sq dist" matrix
__device__ float g_xx[BB][NPTS];
__device__ int   g_knn[BB][NPTS][KNN];
__device__ float g_res[BB][NPTS][256];     // row-major features; blocks write cols [0,64),[64,128),[128,256)
__device__ float g_maxv[BB][NPTS][128];
__device__ float g_minv[BB][NPTS][128];
__device__ float g_z[BB][256][NPTS];       // w3 stage pre-GN output
__device__ float g_ssum[BB * NG];
__device__ float g_ssq[BB * NG];
__device__ float g_pool[BB][512];

// ---------------- xx = sum_c f^2 ----------------
__global__ void xx_kernel(const float* __restrict__ f, long long bs, int rs, int C) {
    int row = blockIdx.x * 8 + (threadIdx.x >> 5);
    int lane = threadIdx.x & 31;
    int b = row / NPTS, n = row % NPTS;
    const float* p = f + (long long)b * bs + (long long)n * rs;
    float s = 0.f;
    for (int c = lane; c < C; c += 32) { float v = p[c]; s += v * v; }
#pragma unroll
    for (int o = 16; o; o >>= 1) s += __shfl_xor_sync(0xffffffffu, s, o);
    if (lane == 0) g_xx[b][n] = s;
}

// ---------------- pd = -(xx_n - 2*dot + xx_m), tiled 64x64 ----------------
template <int C>
__global__ void pd_kernel(const float* __restrict__ f, long long bs, int rs) {
    __shared__ float sA[64][65];
    __shared__ float sB[64][65];
    int b = blockIdx.z;
    int n0 = blockIdx.y * 64, m0 = blockIdx.x * 64;
    int tx = threadIdx.x, ty = threadIdx.y;
    int tid = ty * 16 + tx;
    const float* fb = f + (long long)b * bs;
    for (int t = tid; t < 64 * C; t += 256) {
        int r = t / C, c = t - r * C;
        sA[r][c] = fb[(long long)(n0 + r) * rs + c];
        sB[r][c] = fb[(long long)(m0 + r) * rs + c];
    }
    __syncthreads();
    float acc[4][4];
#pragma unroll
    for (int i = 0; i < 4; ++i)
#pragma unroll
        for (int j = 0; j < 4; ++j) acc[i][j] = 0.f;
#pragma unroll 4
    for (int c = 0; c < C; ++c) {
        float a[4], bv[4];
#pragma unroll
        for (int i = 0; i < 4; ++i) a[i] = sA[ty * 4 + i][c];
#pragma unroll
        for (int j = 0; j < 4; ++j) bv[j] = sB[tx * 4 + j][c];
#pragma unroll
        for (int i = 0; i < 4; ++i)
#pragma unroll
            for (int j = 0; j < 4; ++j) acc[i][j] += a[i] * bv[j];
    }
    float xn[4], xm[4];
#pragma unroll
    for (int i = 0; i < 4; ++i) xn[i] = g_xx[b][n0 + ty * 4 + i];
#pragma unroll
    for (int j = 0; j < 4; ++j) xm[j] = g_xx[b][m0 + tx * 4 + j];
#pragma unroll
    for (int i = 0; i < 4; ++i) {
        float4 o4;
        o4.x = -(xn[i] - 2.f * acc[i][0] + xm[0]);
        o4.y = -(xn[i] - 2.f * acc[i][1] + xm[1]);
        o4.z = -(xn[i] - 2.f * acc[i][2] + xm[2]);
        o4.w = -(xn[i] - 2.f * acc[i][3] + xm[3]);
        *(float4*)&g_pd[b][n0 + ty * 4 + i][m0 + tx * 4] = o4;
    }
}

// ---------------- exact top-K per row (warp per row) ----------------
__global__ void topk_kernel() {
    __shared__ float shv[4][32][KNN];
    __shared__ int   shi[4][32][KNN];
    int w = threadIdx.x >> 5, lane = threadIdx.x & 31;
    int row = blockIdx.x * 4 + w;
    int b = row / NPTS, n = row % NPTS;
    const float* pr = &g_pd[b][n][0];
    float v[KNN]; int idl[KNN];
#pragma unroll
    for (int j = 0; j < KNN; ++j) { v[j] = NEG_INF; idl[j] = 0x7fffffff; }
    for (int m = lane; m < NPTS; m += 32) {
        float x = pr[m];
        if (x > v[KNN - 1]) {
            float cv = x; int ci = m;
#pragma unroll
            for (int j = 0; j < KNN; ++j) {
                bool sw = (cv > v[j]) || (cv == v[j] && ci < idl[j]);
                if (sw) {
                    float tv = v[j]; v[j] = cv; cv = tv;
                    int ti = idl[j]; idl[j] = ci; ci = ti;
                }
            }
        }
    }
#pragma unroll
    for (int j = 0; j < KNN; ++j) { shv[w][lane][j] = v[j]; shi[w][lane][j] = idl[j]; }
    __syncwarp();
    int ptr = 0;
    for (int r = 0; r < KNN; ++r) {
        float hv = (ptr < KNN) ? shv[w][lane][ptr] : NEG_INF;
        int   hi = (ptr < KNN) ? shi[w][lane][ptr] : 0x7fffffff;
        float bv = hv; int bi = hi;
#pragma unroll
        for (int o = 16; o; o >>= 1) {
            float ov = __shfl_xor_sync(0xffffffffu, bv, o);
            int   oi = __shfl_xor_sync(0xffffffffu, bi, o);
            if (ov > bv || (ov == bv && oi < bi)) { bv = ov; bi = oi; }
        }
        if (hv == bv && hi == bi) ptr++;
        if (lane == 0) g_knn[b][n][r] = bi;
    }
}

__global__ void zero_stats() {
    int t = threadIdx.x;
    if (t < BB * NG) { g_ssum[t] = 0.f; g_ssq[t] = 0.f; }
}

// ---------------- fused edge conv + k-max/min + GN stats ----------------
// y[k] = W1 . nbr_k + (W2-W1) . ctr + bias ; reduce over k.
template <int C, int CP, int O, int TN>
__global__ void edgeconv_kernel(const float* __restrict__ f, long long bs, int rs,
                                const float* __restrict__ w, const float* __restrict__ bglob) {
    extern __shared__ float sm[];
    float* w1 = sm;                    // CP*O floats, as float4 blocks [CP/4][O]
    float* w2 = w1 + CP * O;
    float* bsh = w2 + CP * O;          // O
    float* nb = bsh + O;               // 21*CP (20 neighbors + center at k=20)
    float* red = nb + 21 * CP;         // O
    int* sidx = (int*)(red + O);       // KNN

    int o = threadIdx.x;
    int b = blockIdx.y;
    int n0 = blockIdx.x * TN;

#pragma unroll
    for (int c = 0; c < CP; ++c) {
        float a = (c < C) ? w[o * 2 * C + c] : 0.f;
        float d = (c < C) ? (w[o * 2 * C + C + c] - a) : 0.f;
        w1[((c >> 2) * O + o) * 4 + (c & 3)] = a;
        w2[((c >> 2) * O + o) * 4 + (c & 3)] = d;
    }
    bsh[o] = bglob[o];
    __syncthreads();

    const float4* w1v = (const float4*)w1;
    const float4* w2v = (const float4*)w2;
    float ts1 = 0.f, ts2 = 0.f;

    for (int t = 0; t < TN; ++t) {
        int n = n0 + t;
        if (o < KNN) sidx[o] = g_knn[b][n][o];
        __syncthreads();  // sidx ready AND previous compute done with nb
        for (int j = o; j < 21 * CP; j += O) {
            int k = j / CP, c = j - k * CP;
            int m = (k < KNN) ? sidx[k] : n;
            nb[j] = (c < C) ? f[(long long)b * bs + (long long)m * rs + c] : 0.f;
        }
        __syncthreads();

        float ctr_acc = bsh[o];
        const float4* ctr4 = (const float4*)(nb + KNN * CP);
#pragma unroll
        for (int c4 = 0; c4 < CP / 4; ++c4) {
            float4 wv = w2v[c4 * O + o];
            float4 cv = ctr4[c4];
            ctr_acc += wv.x * cv.x + wv.y * cv.y + wv.z * cv.z + wv.w * cv.w;
        }
        float y[KNN];
#pragma unroll
        for (int k = 0; k < KNN; ++k) y[k] = ctr_acc;
#pragma unroll
        for (int c4 = 0; c4 < CP / 4; ++c4) {
            float4 wv = w1v[c4 * O + o];
#pragma unroll
            for (int k = 0; k < KNN; ++k) {
                float4 nv = ((const float4*)(nb + k * CP))[c4];
                y[k] += wv.x * nv.x + wv.y * nv.y + wv.z * nv.z + wv.w * nv.w;
            }
        }
        float mx = y[0], mn = y[0];
#pragma unroll
        for (int k = 0; k < KNN; ++k) {
            mx = fmaxf(mx, y[k]); mn = fminf(mn, y[k]);
            ts1 += y[k]; ts2 += y[k] * y[k];
        }
        g_maxv[b][n][o] = mx;
        g_minv[b][n][o] = mn;
        __syncthreads();  // protect nb before next iteration's gather
    }

    red[o] = ts1; __syncthreads();
    if (o < NG) {
        float s = 0.f;
        for (int i = 0; i < O / NG; ++i) s += red[o * (O / NG) + i];
        atomicAdd(&g_ssum[b * NG + o], s);
    }
    __syncthreads();
    red[o] = ts2; __syncthreads();
    if (o < NG) {
        float s = 0.f;
        for (int i = 0; i < O / NG; ++i) s += red[o * (O / NG) + i];
        atomicAdd(&g_ssq[b * NG + o], s);
    }
}

// ---------------- GN + lrelu applied to the k-extremum, write res ----------------
template <int O>
__global__ void apply_kernel(const float* __restrict__ gamma, const float* __restrict__ beta, int col0) {
    int l = blockIdx.x * blockDim.x + threadIdx.x;  // over BB*NPTS*O
    int o = l % O;
    int n = (l / O) % NPTS;
    int b = l / (O * NPTS);
    int g = o / (O / NG);
    float cnt = (float)(O / NG) * NPTS * KNN;
    float mean = g_ssum[b * NG + g] / cnt;
    float var = fmaxf(g_ssq[b * NG + g] / cnt - mean * mean, 0.f);
    float inv = rsqrtf(var + EPSV);
    float s = gamma[o] * inv;
    float tt = beta[o] - mean * s;
    float sel = (s >= 0.f) ? g_maxv[b][n][o] : g_minv[b][n][o];
    float yv = s * sel + tt;
    g_res[b][n][col0 + o] = (yv >= 0.f) ? yv : 0.2f * yv;
}

// ---------------- pointwise w3 GEMM: z[b][o][n] ----------------
__global__ void w3_gemm(const float* __restrict__ w3, const float* __restrict__ b3) {
    __shared__ float sW[64][17];
    __shared__ float sR[64][17];
    int b = blockIdx.z;
    int o0 = blockIdx.y * 64, n0 = blockIdx.x * 64;
    int tx = threadIdx.x, ty = threadIdx.y;
    int tid = ty * 16 + tx;
    float acc[4][4];
#pragma unroll
    for (int i = 0; i < 4; ++i)
#pragma unroll
        for (int j = 0; j < 4; ++j) acc[i][j] = 0.f;

    for (int c0 = 0; c0 < 256; c0 += 16) {
        for (int t = tid; t < 64 * 16; t += 256) {
            int r = t >> 4, c = t & 15;
            sW[r][c] = w3[(o0 + r) * 256 + c0 + c];
            sR[r][c] = g_res[b][n0 + r][c0 + c];
        }
        __syncthreads();
#pragma unroll
        for (int c = 0; c < 16; ++c) {
            float a[4], bv[4];
#pragma unroll
            for (int i = 0; i < 4; ++i) a[i] = sW[ty * 4 + i][c];
#pragma unroll
            for (int j = 0; j < 4; ++j) bv[j] = sR[tx * 4 + j][c];
#pragma unroll
            for (int i = 0; i < 4; ++i)
#pragma unroll
                for (int j = 0; j < 4; ++j) acc[i][j] += a[i] * bv[j];
        }
        __syncthreads();
    }
#pragma unroll
    for (int i = 0; i < 4; ++i) {
        int o = o0 + ty * 4 + i;
        float bv = b3[o];
        float4 o4 = {acc[i][0] + bv, acc[i][1] + bv, acc[i][2] + bv, acc[i][3] + bv};
        *(float4*)&g_z[b][o][n0 + tx * 4] = o4;
    }
}

// ---------------- stats of z per (b, group) ----------------
__global__ void stats3_kernel() {
    int b = blockIdx.x / NG, g = blockIdx.x % NG;
    int tid = threadIdx.x;
    float s1 = 0.f, s2 = 0.f;
    for (int i = tid; i < 32 * NPTS; i += 256) {
        int o = g * 32 + (i >> 11);
        int n = i & (NPTS - 1);
        float v = g_z[b][o][n];
        s1 += v; s2 += v * v;
    }
    __shared__ float r1[256], r2[256];
    r1[tid] = s1; r2[tid] = s2; __syncthreads();
    for (int st = 128; st; st >>= 1) {
        if (tid < st) { r1[tid] += r1[tid + st]; r2[tid] += r2[tid + st]; }
        __syncthreads();
    }
    if (tid == 0) { g_ssum[b * NG + g] = r1[0]; g_ssq[b * NG + g] = r2[0]; }
}

// ---------------- GN+lrelu+global max/mean pooling ----------------
__global__ void pool_kernel(const float* __restrict__ g3, const float* __restrict__ h3) {
    int b = blockIdx.x >> 8, o = blockIdx.x & 255;
    int g = o >> 5;
    float cnt = 32.f * NPTS;
    float mean = g_ssum[b * NG + g] / cnt;
    float var = fmaxf(g_ssq[b * NG + g] / cnt - mean * mean, 0.f);
    float inv = rsqrtf(var + EPSV);
    float s = g3[o] * inv;
    float tt = h3[o] - mean * s;
    int tid = threadIdx.x;
    float mx = NEG_INF, sum = 0.f;
    for (int n = tid; n < NPTS; n += 256) {
        float v = s * g_z[b][o][n] + tt;
        v = (v >= 0.f) ? v : 0.2f * v;
        mx = fmaxf(mx, v); sum += v;
    }
    __shared__ float rm[256], rs_[256];
    rm[tid] = mx; rs_[tid] = sum; __syncthreads();
    for (int st = 128; st; st >>= 1) {
        if (tid < st) { rm[tid] = fmaxf(rm[tid], rm[tid + st]); rs_[tid] += rs_[tid + st]; }
        __syncthreads();
    }
    if (tid == 0) { g_pool[b][o] = rm[0]; g_pool[b][256 + o] = rs_[0] / (float)NPTS; }
}

// ---------------- FC head (all 3 layers in one kernel, block per batch) ----------------
__global__ void head_kernel(const float* __restrict__ fw0, const float* __restrict__ fb0,
                            const float* __restrict__ fw1, const float* __restrict__ fb1,
                            const float* __restrict__ fw2, const float* __restrict__ fb2,
                            float* __restrict__ out) {
    __shared__ float sv[512];
    int b = blockIdx.x, t = threadIdx.x;
    sv[t] = g_pool[b][t];
    __syncthreads();
    float acc = fb0[t];
    {
        const float4* w4 = (const float4*)(fw0 + t * 512);
        const float4* v4 = (const float4*)sv;
        for (int c4 = 0; c4 < 128; ++c4) {
            float4 w = w4[c4]; float4 v = v4[c4];
            acc += w.x * v.x + w.y * v.y + w.z * v.z + w.w * v.w;
        }
    }
    acc = (acc >= 0.f) ? acc : 0.2f * acc;
    __syncthreads(); sv[t] = acc; __syncthreads();
    acc = fb1[t];
    {
        const float4* w4 = (const float4*)(fw1 + t * 512);
        const float4* v4 = (const float4*)sv;
        for (int c4 = 0; c4 < 128; ++c4) {
            float4 w = w4[c4]; float4 v = v4[c4];
            acc += w.x * v.x + w.y * v.y + w.z * v.z + w.w * v.w;
        }
    }
    acc = (acc >= 0.f) ? acc : 0.2f * acc;
    __syncthreads(); sv[t] = acc; __syncthreads();
    if (t < 256) {
        float a2 = fb2[t];
        const float4* w4 = (const float4*)(fw2 + t * 512);
        const float4* v4 = (const float4*)sv;
        for (int c4 = 0; c4 < 128; ++c4) {
            float4 w = w4[c4]; float4 v = v4[c4];
            a2 += w.x * v.x + w.y * v.y + w.z * v.z + w.w * v.w;
        }
        out[b * 256 + t] = a2;
    }
}

static inline size_t ec_smem(int CP, int O) {
    return (size_t)(2 * CP * O + 2 * O + 21 * CP) * 4 + KNN * 4 + 16;
}

extern "C" void kernel_launch(void* const* d_in, const int* in_sizes, int n_in,
                              void* d_out, int out_size) {
    const float* x  = (const float*)d_in[0];
    const float* w0 = (const float*)d_in[1];
    const float* b0 = (const float*)d_in[2];
    const float* g0 = (const float*)d_in[3];
    const float* h0 = (const float*)d_in[4];
    const float* w1 = (const float*)d_in[5];
    const float* b1 = (const float*)d_in[6];
    const float* g1 = (const float*)d_in[7];
    const float* h1 = (const float*)d_in[8];
    const float* w2 = (const float*)d_in[9];
    const float* b2 = (const float*)d_in[10];
    const float* g2 = (const float*)d_in[11];
    const float* h2 = (const float*)d_in[12];
    const float* w3 = (const float*)d_in[13];
    const float* b3 = (const float*)d_in[14];
    const float* g3 = (const float*)d_in[15];
    const float* h3 = (const float*)d_in[16];
    const float* fw0 = (const float*)d_in[17];
    const float* fb0 = (const float*)d_in[18];
    const float* fw1 = (const float*)d_in[19];
    const float* fb1 = (const float*)d_in[20];
    const float* fw2 = (const float*)d_in[21];
    const float* fb2 = (const float*)d_in[22];
    float* out = (float*)d_out;

    float* resp = nullptr;
    cudaGetSymbolAddress((void**)&resp, g_res);

    cudaFuncSetAttribute(edgeconv_kernel<64, 64, 128, 8>,
                         cudaFuncAttributeMaxDynamicSharedMemorySize, 128 * 1024);
    cudaFuncSetAttribute(edgeconv_kernel<64, 64, 64, 8>,
                         cudaFuncAttributeMaxDynamicSharedMemorySize, 64 * 1024);

    dim3 pdgrid(NPTS / 64, NPTS / 64, BB), pdblk(16, 16);

    // ---------- stage 1: C=3 -> O=64, res cols [0,64) ----------
    {
        long long bs = (long long)NPTS * 3;
        xx_kernel<<<BB * NPTS / 8, 256>>>(x, bs, 3, 3);
        pd_kernel<3><<<pdgrid, pdblk>>>(x, bs, 3);
        topk_kernel<<<BB * NPTS / 4, 128>>>();
        zero_stats<<<1, 64>>>();
        edgeconv_kernel<3, 4, 64, 8><<<dim3(NPTS / 8, BB), 64, ec_smem(4, 64)>>>(x, bs, 3, w0, b0);
        apply_kernel<64><<<BB * NPTS * 64 / 256, 256>>>(g0, h0, 0);
    }
    // ---------- stage 2: C=64 (cols 0..63) -> O=64, res cols [64,128) ----------
    {
        long long bs = (long long)NPTS * 256;
        xx_kernel<<<BB * NPTS / 8, 256>>>(resp, bs, 256, 64);
        pd_kernel<64><<<pdgrid, pdblk>>>(resp, bs, 256);
        topk_kernel<<<BB * NPTS / 4, 128>>>();
        zero_stats<<<1, 64>>>();
        edgeconv_kernel<64, 64, 64, 8><<<dim3(NPTS / 8, BB), 64, ec_smem(64, 64)>>>(resp, bs, 256, w1, b1);
        apply_kernel<64><<<BB * NPTS * 64 / 256, 256>>>(g1, h1, 64);
    }
    // ---------- stage 3: C=64 (cols 64..127) -> O=128, res cols [128,256) ----------
    {
        long long bs = (long long)NPTS * 256;
        const float* f = resp + 64;
        xx_kernel<<<BB * NPTS / 8, 256>>>(f, bs, 256, 64);
        pd_kernel<64><<<pdgrid, pdblk>>>(f, bs, 256);
        topk_kernel<<<BB * NPTS / 4, 128>>>();
        zero_stats<<<1, 64>>>();
        edgeconv_kernel<64, 64, 128, 8><<<dim3(NPTS / 8, BB), 128, ec_smem(64, 128)>>>(f, bs, 256, w2, b2);
        apply_kernel<128><<<BB * NPTS * 128 / 256, 256>>>(g2, h2, 128);
    }
    // ---------- w3 pointwise + GN + pool + head ----------
    w3_gemm<<<dim3(NPTS / 64, 256 / 64, BB), dim3(16, 16)>>>(w3, b3);
    stats3_kernel<<<BB * NG, 256>>>();
    pool_kernel<<<BB * 256, 256>>>(g3, h3);
    head_kernel<<<BB, 512>>>(fw0, fb0, fw1, fb1, fw2, fb2, out);
}

// round 2
// speedup vs baseline: 1.4798x; 1.4798x over previous
#include <cuda_runtime.h>

#define BB 8
#define NPTS 2048
#define KNN 20
#define NG 8
#define EPSV 1e-5f

#define NEG_INF __int_as_float(0xff800000)
#define POS_INF __int_as_float(0x7f800000)

// ---------------- device scratch ----------------
__device__ float g_pd[BB][NPTS][NPTS];
__device__ float g_xx[BB][NPTS];
__device__ int   g_knn[BB][NPTS][KNN];
__device__ float g_res[BB][NPTS][256];
__device__ float g_U[BB][NPTS][128];
__device__ float g_V[BB][NPTS][128];
__device__ float g_maxv[BB][NPTS][128];
__device__ float g_minv[BB][NPTS][128];
__device__ float g_z[BB][256][NPTS];
__device__ float g_ssum[BB * NG];
__device__ float g_ssq[BB * NG];
__device__ float g_pool[BB][512];

// ---------------- xx = sum_c f^2 ----------------
__global__ void xx_kernel(const float* __restrict__ f, long long bs, int rs, int C) {
    int row = blockIdx.x * 8 + (threadIdx.x >> 5);
    int lane = threadIdx.x & 31;
    int b = row / NPTS, n = row % NPTS;
    const float* p = f + (long long)b * bs + (long long)n * rs;
    float s = 0.f;
    for (int c = lane; c < C; c += 32) { float v = p[c]; s += v * v; }
#pragma unroll
    for (int o = 16; o; o >>= 1) s += __shfl_xor_sync(0xffffffffu, s, o);
    if (lane == 0) g_xx[b][n] = s;
}

// ---------------- pd = -(xx_n - 2*dot + xx_m), 64x64 tile, transposed smem ----------------
template <int C>
__global__ void pd_kernel(const float* __restrict__ f, long long bs, int rs) {
    constexpr int KT = (C < 32) ? C : 32;
    __shared__ float sA[KT][68];
    __shared__ float sB[KT][68];
    int b = blockIdx.z;
    int n0 = blockIdx.y * 64, m0 = blockIdx.x * 64;
    int tx = threadIdx.x, ty = threadIdx.y;
    int tid = ty * 16 + tx;
    const float* fb = f + (long long)b * bs;
    float acc[4][4];
#pragma unroll
    for (int i = 0; i < 4; ++i)
#pragma unroll
        for (int j = 0; j < 4; ++j) acc[i][j] = 0.f;

    for (int k0 = 0; k0 < C; k0 += KT) {
        for (int t = tid; t < 64 * KT; t += 256) {
            int r = t / KT, c = t - r * KT;
            sA[c][r] = fb[(long long)(n0 + r) * rs + k0 + c];
            sB[c][r] = fb[(long long)(m0 + r) * rs + k0 + c];
        }
        __syncthreads();
#pragma unroll
        for (int c = 0; c < KT; ++c) {
            float4 a4 = *(const float4*)&sA[c][ty * 4];
            float4 b4 = *(const float4*)&sB[c][tx * 4];
            float a[4] = {a4.x, a4.y, a4.z, a4.w};
            float bv[4] = {b4.x, b4.y, b4.z, b4.w};
#pragma unroll
            for (int i = 0; i < 4; ++i)
#pragma unroll
                for (int j = 0; j < 4; ++j) acc[i][j] += a[i] * bv[j];
        }
        __syncthreads();
    }
    float xn[4], xm[4];
#pragma unroll
    for (int i = 0; i < 4; ++i) xn[i] = g_xx[b][n0 + ty * 4 + i];
#pragma unroll
    for (int j = 0; j < 4; ++j) xm[j] = g_xx[b][m0 + tx * 4 + j];
#pragma unroll
    for (int i = 0; i < 4; ++i) {
        float4 o4;
        o4.x = -(xn[i] - 2.f * acc[i][0] + xm[0]);
        o4.y = -(xn[i] - 2.f * acc[i][1] + xm[1]);
        o4.z = -(xn[i] - 2.f * acc[i][2] + xm[2]);
        o4.w = -(xn[i] - 2.f * acc[i][3] + xm[3]);
        *(float4*)&g_pd[b][n0 + ty * 4 + i][m0 + tx * 4] = o4;
    }
}

// ---------------- exact top-K per row (warp per row), float4 row reads ----------------
__global__ void topk_kernel() {
    __shared__ float shv[4][32][KNN];
    __shared__ int   shi[4][32][KNN];
    int w = threadIdx.x >> 5, lane = threadIdx.x & 31;
    int row = blockIdx.x * 4 + w;
    int b = row / NPTS, n = row % NPTS;
    const float4* pr4 = (const float4*)&g_pd[b][n][0];
    float v[KNN]; int idl[KNN];
#pragma unroll
    for (int j = 0; j < KNN; ++j) { v[j] = NEG_INF; idl[j] = 0x7fffffff; }
    for (int i = lane; i < NPTS / 4; i += 32) {
        float4 x4 = pr4[i];
        float xs[4] = {x4.x, x4.y, x4.z, x4.w};
#pragma unroll
        for (int q = 0; q < 4; ++q) {
            float x = xs[q];
            if (x > v[KNN - 1]) {
                float cv = x; int ci = i * 4 + q;
#pragma unroll
                for (int j = 0; j < KNN; ++j) {
                    bool sw = (cv > v[j]) || (cv == v[j] && ci < idl[j]);
                    if (sw) {
                        float tv = v[j]; v[j] = cv; cv = tv;
                        int ti = idl[j]; idl[j] = ci; ci = ti;
                    }
                }
            }
        }
    }
#pragma unroll
    for (int j = 0; j < KNN; ++j) { shv[w][lane][j] = v[j]; shi[w][lane][j] = idl[j]; }
    __syncwarp();
    int ptr = 0;
    for (int r = 0; r < KNN; ++r) {
        float hv = (ptr < KNN) ? shv[w][lane][ptr] : NEG_INF;
        int   hi = (ptr < KNN) ? shi[w][lane][ptr] : 0x7fffffff;
        float bv = hv; int bi = hi;
#pragma unroll
        for (int o = 16; o; o >>= 1) {
            float ov = __shfl_xor_sync(0xffffffffu, bv, o);
            int   oi = __shfl_xor_sync(0xffffffffu, bi, o);
            if (ov > bv || (ov == bv && oi < bi)) { bv = ov; bi = oi; }
        }
        if (hv == bv && hi == bi) ptr++;
        if (lane == 0) g_knn[b][n][r] = bi;
    }
}

__global__ void zero_stats() {
    int t = threadIdx.x;
    if (t < BB * NG) { g_ssum[t] = 0.f; g_ssq[t] = 0.f; }
}

// ---------------- U = f*W1^T, V = f*(W2-W1)^T + b ----------------
template <int C>
__global__ void uv_gemm(const float* __restrict__ f, long long bs, int rs,
                        const float* __restrict__ w, const float* __restrict__ bias) {
    constexpr int KT = (C < 32) ? C : 32;
    __shared__ float sF[KT][68];
    __shared__ float sW1[KT][68];
    __shared__ float sDW[KT][68];
    int b = blockIdx.y;
    int n0 = blockIdx.x * 64;
    int o0 = blockIdx.z * 64;
    int tx = threadIdx.x, ty = threadIdx.y;
    int tid = ty * 16 + tx;
    const float* fb = f + (long long)b * bs;
    float au[4][4], av[4][4];
#pragma unroll
    for (int i = 0; i < 4; ++i)
#pragma unroll
        for (int j = 0; j < 4; ++j) { au[i][j] = 0.f; av[i][j] = 0.f; }

    for (int k0 = 0; k0 < C; k0 += KT) {
        for (int t = tid; t < 64 * KT; t += 256) {
            int r = t / KT, c = t - r * KT;
            sF[c][r] = fb[(long long)(n0 + r) * rs + k0 + c];
            float w1 = w[(o0 + r) * 2 * C + k0 + c];
            float w2 = w[(o0 + r) * 2 * C + C + k0 + c];
            sW1[c][r] = w1; sDW[c][r] = w2 - w1;
        }
        __syncthreads();
#pragma unroll
        for (int c = 0; c < KT; ++c) {
            float4 f4 = *(const float4*)&sF[c][ty * 4];
            float4 w4 = *(const float4*)&sW1[c][tx * 4];
            float4 d4 = *(const float4*)&sDW[c][tx * 4];
            float a[4] = {f4.x, f4.y, f4.z, f4.w};
            float wv[4] = {w4.x, w4.y, w4.z, w4.w};
            float dv[4] = {d4.x, d4.y, d4.z, d4.w};
#pragma unroll
            for (int i = 0; i < 4; ++i)
#pragma unroll
                for (int j = 0; j < 4; ++j) {
                    au[i][j] += a[i] * wv[j];
                    av[i][j] += a[i] * dv[j];
                }
        }
        __syncthreads();
    }
    float bb0 = bias[o0 + tx * 4 + 0];
    float bb1 = bias[o0 + tx * 4 + 1];
    float bb2 = bias[o0 + tx * 4 + 2];
    float bb3 = bias[o0 + tx * 4 + 3];
#pragma unroll
    for (int i = 0; i < 4; ++i) {
        int n = n0 + ty * 4 + i;
        float4 u4 = {au[i][0], au[i][1], au[i][2], au[i][3]};
        float4 v4 = {av[i][0] + bb0, av[i][1] + bb1, av[i][2] + bb2, av[i][3] + bb3};
        *(float4*)&g_U[b][n][o0 + tx * 4] = u4;
        *(float4*)&g_V[b][n][o0 + tx * 4] = v4;
    }
}

// ---------------- gather + k-max/min + GN stats ----------------
template <int O, int P>
__global__ void gather_reduce() {
    constexpr int PY = 256 / O;
    __shared__ int sidx[P][KNN];
    __shared__ float red[256];
    int o = threadIdx.x, py = threadIdx.y;
    int t = py * O + o;
    int b = blockIdx.y, n0 = blockIdx.x * P;
    for (int j = t; j < P * KNN; j += 256)
        sidx[j / KNN][j % KNN] = g_knn[b][n0 + j / KNN][j % KNN];
    __syncthreads();
    float ts1 = 0.f, ts2 = 0.f;
    for (int p = py; p < P; p += PY) {
        int n = n0 + p;
        float v = g_V[b][n][o];
        float mx = NEG_INF, mn = POS_INF;
#pragma unroll
        for (int k = 0; k < KNN; ++k) {
            float y = g_U[b][sidx[p][k]][o] + v;
            mx = fmaxf(mx, y); mn = fminf(mn, y);
            ts1 += y; ts2 += y * y;
        }
        g_maxv[b][n][o] = mx;
        g_minv[b][n][o] = mn;
    }
    red[t] = ts1; __syncthreads();
    if (t < NG) {
        float s = 0.f;
        for (int pp = 0; pp < PY; ++pp)
            for (int i = 0; i < O / NG; ++i) s += red[pp * O + t * (O / NG) + i];
        atomicAdd(&g_ssum[b * NG + t], s);
    }
    __syncthreads();
    red[t] = ts2; __syncthreads();
    if (t < NG) {
        float s = 0.f;
        for (int pp = 0; pp < PY; ++pp)
            for (int i = 0; i < O / NG; ++i) s += red[pp * O + t * (O / NG) + i];
        atomicAdd(&g_ssq[b * NG + t], s);
    }
}

// ---------------- GN + lrelu applied to k-extremum ----------------
template <int O>
__global__ void apply_kernel(const float* __restrict__ gamma, const float* __restrict__ beta, int col0) {
    int l = blockIdx.x * blockDim.x + threadIdx.x;
    int o = l % O;
    int n = (l / O) % NPTS;
    int b = l / (O * NPTS);
    int g = o / (O / NG);
    float cnt = (float)(O / NG) * NPTS * KNN;
    float mean = g_ssum[b * NG + g] / cnt;
    float var = fmaxf(g_ssq[b * NG + g] / cnt - mean * mean, 0.f);
    float inv = rsqrtf(var + EPSV);
    float s = gamma[o] * inv;
    float tt = beta[o] - mean * s;
    float sel = (s >= 0.f) ? g_maxv[b][n][o] : g_minv[b][n][o];
    float yv = s * sel + tt;
    g_res[b][n][col0 + o] = (yv >= 0.f) ? yv : 0.2f * yv;
}

// ---------------- w3 pointwise GEMM: z[b][o][n], transposed smem ----------------
__global__ void w3_gemm(const float* __restrict__ w3, const float* __restrict__ b3) {
    __shared__ float sW[32][68];
    __shared__ float sR[32][68];
    int b = blockIdx.z;
    int o0 = blockIdx.y * 64, n0 = blockIdx.x * 64;
    int tx = threadIdx.x, ty = threadIdx.y;
    int tid = ty * 16 + tx;
    float acc[4][4];
#pragma unroll
    for (int i = 0; i < 4; ++i)
#pragma unroll
        for (int j = 0; j < 4; ++j) acc[i][j] = 0.f;

    for (int k0 = 0; k0 < 256; k0 += 32) {
        for (int t = tid; t < 64 * 32; t += 256) {
            int r = t >> 5, c = t & 31;
            sW[c][r] = w3[(o0 + r) * 256 + k0 + c];
            sR[c][r] = g_res[b][n0 + r][k0 + c];
        }
        __syncthreads();
#pragma unroll
        for (int c = 0; c < 32; ++c) {
            float4 a4 = *(const float4*)&sW[c][ty * 4];
            float4 b4 = *(const float4*)&sR[c][tx * 4];
            float a[4] = {a4.x, a4.y, a4.z, a4.w};
            float bv[4] = {b4.x, b4.y, b4.z, b4.w};
#pragma unroll
            for (int i = 0; i < 4; ++i)
#pragma unroll
                for (int j = 0; j < 4; ++j) acc[i][j] += a[i] * bv[j];
        }
        __syncthreads();
    }
#pragma unroll
    for (int i = 0; i < 4; ++i) {
        int o = o0 + ty * 4 + i;
        float bv = b3[o];
        float4 o4 = {acc[i][0] + bv, acc[i][1] + bv, acc[i][2] + bv, acc[i][3] + bv};
        *(float4*)&g_z[b][o][n0 + tx * 4] = o4;
    }
}

// ---------------- stats of z per (b, group) ----------------
__global__ void stats3_kernel() {
    int b = blockIdx.x / NG, g = blockIdx.x % NG;
    int tid = threadIdx.x;
    float s1 = 0.f, s2 = 0.f;
    for (int i = tid; i < 32 * NPTS; i += 256) {
        int o = g * 32 + (i >> 11);
        int n = i & (NPTS - 1);
        float v = g_z[b][o][n];
        s1 += v; s2 += v * v;
    }
    __shared__ float r1[256], r2[256];
    r1[tid] = s1; r2[tid] = s2; __syncthreads();
    for (int st = 128; st; st >>= 1) {
        if (tid < st) { r1[tid] += r1[tid + st]; r2[tid] += r2[tid + st]; }
        __syncthreads();
    }
    if (tid == 0) { g_ssum[b * NG + g] = r1[0]; g_ssq[b * NG + g] = r2[0]; }
}

// ---------------- GN+lrelu+global max/mean pooling ----------------
__global__ void pool_kernel(const float* __restrict__ g3, const float* __restrict__ h3) {
    int b = blockIdx.x >> 8, o = blockIdx.x & 255;
    int g = o >> 5;
    float cnt = 32.f * NPTS;
    float mean = g_ssum[b * NG + g] / cnt;
    float var = fmaxf(g_ssq[b * NG + g] / cnt - mean * mean, 0.f);
    float inv = rsqrtf(var + EPSV);
    float s = g3[o] * inv;
    float tt = h3[o] - mean * s;
    int tid = threadIdx.x;
    float mx = NEG_INF, sum = 0.f;
    for (int n = tid; n < NPTS; n += 256) {
        float v = s * g_z[b][o][n] + tt;
        v = (v >= 0.f) ? v : 0.2f * v;
        mx = fmaxf(mx, v); sum += v;
    }
    __shared__ float rm[256], rs_[256];
    rm[tid] = mx; rs_[tid] = sum; __syncthreads();
    for (int st = 128; st; st >>= 1) {
        if (tid < st) { rm[tid] = fmaxf(rm[tid], rm[tid + st]); rs_[tid] += rs_[tid + st]; }
        __syncthreads();
    }
    if (tid == 0) { g_pool[b][o] = rm[0]; g_pool[b][256 + o] = rs_[0] / (float)NPTS; }
}

// ---------------- FC head ----------------
__global__ void head_kernel(const float* __restrict__ fw0, const float* __restrict__ fb0,
                            const float* __restrict__ fw1, const float* __restrict__ fb1,
                            const float* __restrict__ fw2, const float* __restrict__ fb2,
                            float* __restrict__ out) {
    __shared__ float sv[512];
    int b = blockIdx.x, t = threadIdx.x;
    sv[t] = g_pool[b][t];
    __syncthreads();
    float acc = fb0[t];
    {
        const float4* w4 = (const float4*)(fw0 + t * 512);
        const float4* v4 = (const float4*)sv;
        for (int c4 = 0; c4 < 128; ++c4) {
            float4 w = w4[c4]; float4 v = v4[c4];
            acc += w.x * v.x + w.y * v.y + w.z * v.z + w.w * v.w;
        }
    }
    acc = (acc >= 0.f) ? acc : 0.2f * acc;
    __syncthreads(); sv[t] = acc; __syncthreads();
    acc = fb1[t];
    {
        const float4* w4 = (const float4*)(fw1 + t * 512);
        const float4* v4 = (const float4*)sv;
        for (int c4 = 0; c4 < 128; ++c4) {
            float4 w = w4[c4]; float4 v = v4[c4];
            acc += w.x * v.x + w.y * v.y + w.z * v.z + w.w * v.w;
        }
    }
    acc = (acc >= 0.f) ? acc : 0.2f * acc;
    __syncthreads(); sv[t] = acc; __syncthreads();
    if (t < 256) {
        float a2 = fb2[t];
        const float4* w4 = (const float4*)(fw2 + t * 512);
        const float4* v4 = (const float4*)sv;
        for (int c4 = 0; c4 < 128; ++c4) {
            float4 w = w4[c4]; float4 v = v4[c4];
            a2 += w.x * v.x + w.y * v.y + w.z * v.z + w.w * v.w;
        }
        out[b * 256 + t] = a2;
    }
}

extern "C" void kernel_launch(void* const* d_in, const int* in_sizes, int n_in,
                              void* d_out, int out_size) {
    const float* x  = (const float*)d_in[0];
    const float* w0 = (const float*)d_in[1];
    const float* b0 = (const float*)d_in[2];
    const float* g0 = (const float*)d_in[3];
    const float* h0 = (const float*)d_in[4];
    const float* w1 = (const float*)d_in[5];
    const float* b1 = (const float*)d_in[6];
    const float* g1 = (const float*)d_in[7];
    const float* h1 = (const float*)d_in[8];
    const float* w2 = (const float*)d_in[9];
    const float* b2 = (const float*)d_in[10];
    const float* g2 = (const float*)d_in[11];
    const float* h2 = (const float*)d_in[12];
    const float* w3 = (const float*)d_in[13];
    const float* b3 = (const float*)d_in[14];
    const float* g3 = (const float*)d_in[15];
    const float* h3 = (const float*)d_in[16];
    const float* fw0 = (const float*)d_in[17];
    const float* fb0 = (const float*)d_in[18];
    const float* fw1 = (const float*)d_in[19];
    const float* fb1 = (const float*)d_in[20];
    const float* fw2 = (const float*)d_in[21];
    const float* fb2 = (const float*)d_in[22];
    float* out = (float*)d_out;

    float* resp = nullptr;
    cudaGetSymbolAddress((void**)&resp, g_res);

    dim3 pdgrid(NPTS / 64, NPTS / 64, BB), blk16(16, 16);

    // ---------- stage 1: C=3 -> O=64, res cols [0,64) ----------
    {
        long long bs = (long long)NPTS * 3;
        xx_kernel<<<BB * NPTS / 8, 256>>>(x, bs, 3, 3);
        pd_kernel<3><<<pdgrid, blk16>>>(x, bs, 3);
        topk_kernel<<<BB * NPTS / 4, 128>>>();
        zero_stats<<<1, 64>>>();
        uv_gemm<3><<<dim3(NPTS / 64, BB, 1), blk16>>>(x, bs, 3, w0, b0);
        gather_reduce<64, 16><<<dim3(NPTS / 16, BB), dim3(64, 4)>>>();
        apply_kernel<64><<<BB * NPTS * 64 / 256, 256>>>(g0, h0, 0);
    }
    // ---------- stage 2: C=64 (cols 0..63) -> O=64, res cols [64,128) ----------
    {
        long long bs = (long long)NPTS * 256;
        xx_kernel<<<BB * NPTS / 8, 256>>>(resp, bs, 256, 64);
        pd_kernel<64><<<pdgrid, blk16>>>(resp, bs, 256);
        topk_kernel<<<BB * NPTS / 4, 128>>>();
        zero_stats<<<1, 64>>>();
        uv_gemm<64><<<dim3(NPTS / 64, BB, 1), blk16>>>(resp, bs, 256, w1, b1);
        gather_reduce<64, 16><<<dim3(NPTS / 16, BB), dim3(64, 4)>>>();
        apply_kernel<64><<<BB * NPTS * 64 / 256, 256>>>(g1, h1, 64);
    }
    // ---------- stage 3: C=64 (cols 64..127) -> O=128, res cols [128,256) ----------
    {
        long long bs = (long long)NPTS * 256;
        const float* f = resp + 64;
        xx_kernel<<<BB * NPTS / 8, 256>>>(f, bs, 256, 64);
        pd_kernel<64><<<pdgrid, blk16>>>(f, bs, 256);
        topk_kernel<<<BB * NPTS / 4, 128>>>();
        zero_stats<<<1, 64>>>();
        uv_gemm<64><<<dim3(NPTS / 64, BB, 2), blk16>>>(f, bs, 256, w2, b2);
        gather_reduce<128, 8><<<dim3(NPTS / 8, BB), dim3(128, 2)>>>();
        apply_kernel<128><<<BB * NPTS * 128 / 256, 256>>>(g2, h2, 128);
    }
    // ---------- w3 pointwise + GN + pool + head ----------
    w3_gemm<<<dim3(NPTS / 64, 256 / 64, BB), blk16>>>(w3, b3);
    stats3_kernel<<<BB * NG, 256>>>();
    pool_kernel<<<BB * 256, 256>>>(g3, h3);
    head_kernel<<<BB, 512>>>(fw0, fb0, fw1, fb1, fw2, fb2, out);
}

// round 3
// speedup vs baseline: 1.8730x; 1.2657x over previous
#include <cuda_runtime.h>

#define BB 8
#define NPTS 2048
#define KNN 20
#define NG 8
#define EPSV 1e-5f

#define NEG_INF __int_as_float(0xff800000)
#define POS_INF __int_as_float(0x7f800000)

// ---------------- device scratch ----------------
__device__ float g_pd[BB][NPTS][NPTS];
__device__ float g_xx[BB][NPTS];
__device__ int   g_knn[BB][NPTS][KNN];
__device__ float g_res[BB][NPTS][256];
__device__ float g_U[BB][NPTS][128];
__device__ float g_V[BB][NPTS][128];
__device__ float g_maxv[BB][NPTS][128];
__device__ float g_minv[BB][NPTS][128];
__device__ float g_z[BB][256][NPTS];
__device__ float g_ssum[BB * NG];
__device__ float g_ssq[BB * NG];
__device__ float g_pool[BB][512];

// ---------------- xx = sum_c f^2 (+ zero the stage stats) ----------------
__global__ void xx_kernel(const float* __restrict__ f, long long bs, int rs, int C) {
    if (blockIdx.x == 0 && threadIdx.x < BB * NG) {
        g_ssum[threadIdx.x] = 0.f; g_ssq[threadIdx.x] = 0.f;
    }
    int row = blockIdx.x * 8 + (threadIdx.x >> 5);
    int lane = threadIdx.x & 31;
    int b = row / NPTS, n = row % NPTS;
    const float* p = f + (long long)b * bs + (long long)n * rs;
    float s = 0.f;
    for (int c = lane; c < C; c += 32) { float v = p[c]; s += v * v; }
#pragma unroll
    for (int o = 16; o; o >>= 1) s += __shfl_xor_sync(0xffffffffu, s, o);
    if (lane == 0) g_xx[b][n] = s;
}

// ---------------- pd (C=3 path): 64x64 tile ----------------
template <int C>
__global__ void pd_kernel(const float* __restrict__ f, long long bs, int rs) {
    constexpr int KT = (C < 32) ? C : 32;
    __shared__ float sA[KT][68];
    __shared__ float sB[KT][68];
    int b = blockIdx.z;
    int n0 = blockIdx.y * 64, m0 = blockIdx.x * 64;
    int tx = threadIdx.x, ty = threadIdx.y;
    int tid = ty * 16 + tx;
    const float* fb = f + (long long)b * bs;
    float acc[4][4];
#pragma unroll
    for (int i = 0; i < 4; ++i)
#pragma unroll
        for (int j = 0; j < 4; ++j) acc[i][j] = 0.f;

    for (int k0 = 0; k0 < C; k0 += KT) {
        for (int t = tid; t < 64 * KT; t += 256) {
            int r = t / KT, c = t - r * KT;
            sA[c][r] = fb[(long long)(n0 + r) * rs + k0 + c];
            sB[c][r] = fb[(long long)(m0 + r) * rs + k0 + c];
        }
        __syncthreads();
#pragma unroll
        for (int c = 0; c < KT; ++c) {
            float4 a4 = *(const float4*)&sA[c][ty * 4];
            float4 b4 = *(const float4*)&sB[c][tx * 4];
            float a[4] = {a4.x, a4.y, a4.z, a4.w};
            float bv[4] = {b4.x, b4.y, b4.z, b4.w};
#pragma unroll
            for (int i = 0; i < 4; ++i)
#pragma unroll
                for (int j = 0; j < 4; ++j) acc[i][j] += a[i] * bv[j];
        }
        __syncthreads();
    }
    float xn[4], xm[4];
#pragma unroll
    for (int i = 0; i < 4; ++i) xn[i] = g_xx[b][n0 + ty * 4 + i];
#pragma unroll
    for (int j = 0; j < 4; ++j) xm[j] = g_xx[b][m0 + tx * 4 + j];
#pragma unroll
    for (int i = 0; i < 4; ++i) {
        float4 o4;
        o4.x = -(xn[i] - 2.f * acc[i][0] + xm[0]);
        o4.y = -(xn[i] - 2.f * acc[i][1] + xm[1]);
        o4.z = -(xn[i] - 2.f * acc[i][2] + xm[2]);
        o4.w = -(xn[i] - 2.f * acc[i][3] + xm[3]);
        *(float4*)&g_pd[b][n0 + ty * 4 + i][m0 + tx * 4] = o4;
    }
}

// ---------------- pd (C=64 path): 128x128 tile, 8x8 per thread ----------------
__global__ void pd_kernel128(const float* __restrict__ f, long long bs, int rs) {
    __shared__ float sA[32][132];
    __shared__ float sB[32][132];
    int b = blockIdx.z;
    int n0 = blockIdx.y * 128, m0 = blockIdx.x * 128;
    int tx = threadIdx.x, ty = threadIdx.y;
    int tid = ty * 16 + tx;
    const float* fb = f + (long long)b * bs;
    float acc[8][8];
#pragma unroll
    for (int i = 0; i < 8; ++i)
#pragma unroll
        for (int j = 0; j < 8; ++j) acc[i][j] = 0.f;

    for (int k0 = 0; k0 < 64; k0 += 32) {
        for (int t = tid; t < 128 * 32; t += 256) {
            int r = t >> 5, c = t & 31;
            sA[c][r] = fb[(long long)(n0 + r) * rs + k0 + c];
            sB[c][r] = fb[(long long)(m0 + r) * rs + k0 + c];
        }
        __syncthreads();
#pragma unroll
        for (int c = 0; c < 32; ++c) {
            float4 a0 = *(const float4*)&sA[c][ty * 8];
            float4 a1 = *(const float4*)&sA[c][ty * 8 + 4];
            float4 b0 = *(const float4*)&sB[c][tx * 8];
            float4 b1 = *(const float4*)&sB[c][tx * 8 + 4];
            float a[8] = {a0.x, a0.y, a0.z, a0.w, a1.x, a1.y, a1.z, a1.w};
            float bv[8] = {b0.x, b0.y, b0.z, b0.w, b1.x, b1.y, b1.z, b1.w};
#pragma unroll
            for (int i = 0; i < 8; ++i)
#pragma unroll
                for (int j = 0; j < 8; ++j) acc[i][j] += a[i] * bv[j];
        }
        __syncthreads();
    }
    float xn[8], xm[8];
#pragma unroll
    for (int i = 0; i < 8; ++i) xn[i] = g_xx[b][n0 + ty * 8 + i];
#pragma unroll
    for (int j = 0; j < 8; ++j) xm[j] = g_xx[b][m0 + tx * 8 + j];
#pragma unroll
    for (int i = 0; i < 8; ++i) {
        int n = n0 + ty * 8 + i;
        float4 o4;
        o4.x = -(xn[i] - 2.f * acc[i][0] + xm[0]);
        o4.y = -(xn[i] - 2.f * acc[i][1] + xm[1]);
        o4.z = -(xn[i] - 2.f * acc[i][2] + xm[2]);
        o4.w = -(xn[i] - 2.f * acc[i][3] + xm[3]);
        *(float4*)&g_pd[b][n][m0 + tx * 8] = o4;
        o4.x = -(xn[i] - 2.f * acc[i][4] + xm[4]);
        o4.y = -(xn[i] - 2.f * acc[i][5] + xm[5]);
        o4.z = -(xn[i] - 2.f * acc[i][6] + xm[6]);
        o4.w = -(xn[i] - 2.f * acc[i][7] + xm[7]);
        *(float4*)&g_pd[b][n][m0 + tx * 8 + 4] = o4;
    }
}

// ---------------- exact top-K SET per row: warp threshold + replace-min ----------------
__global__ void topk_kernel() {
    __shared__ float sv[4][640];
    __shared__ int   si[4][640];
    __shared__ int   scnt[4];
    int w = threadIdx.x >> 5, lane = threadIdx.x & 31;
    int row = blockIdx.x * 4 + w;
    int b = row / NPTS, n = row % NPTS;
    const float4* pr4 = (const float4*)&g_pd[b][n][0];

    float v[KNN]; int idl[KNN];
#pragma unroll
    for (int j = 0; j < KNN; ++j) { v[j] = NEG_INF; idl[j] = 0; }
    float lmin = NEG_INF; int lslot = 0;
    float T = NEG_INF;

    for (int i = lane; i < NPTS / 4; i += 32) {
        float4 x4 = pr4[i];
        float xs[4] = {x4.x, x4.y, x4.z, x4.w};
#pragma unroll
        for (int q = 0; q < 4; ++q) {
            float x = xs[q];
            if (x >= T && x > lmin) {
                v[lslot] = x; idl[lslot] = i * 4 + q;
                lmin = v[0]; lslot = 0;
#pragma unroll
                for (int j = 1; j < KNN; ++j)
                    if (v[j] < lmin) { lmin = v[j]; lslot = j; }
            }
        }
        float t = lmin;
#pragma unroll
        for (int o = 16; o; o >>= 1) t = fmaxf(t, __shfl_xor_sync(0xffffffffu, t, o));
        T = t;
    }

    // compact survivors (>= T) to shared
    if (lane == 0) scnt[w] = 0;
    __syncwarp();
#pragma unroll
    for (int j = 0; j < KNN; ++j) {
        if (v[j] >= T) {
            int p = atomicAdd(&scnt[w], 1);
            sv[w][p] = v[j]; si[w][p] = idl[j];
        }
    }
    __syncwarp();
    int cnt = scnt[w];

    // extract top-20 by repeated warp argmax
    for (int r = 0; r < KNN; ++r) {
        float bv = NEG_INF; int bi = 0x7fffffff; int bp = -1;
        for (int p = lane; p < cnt; p += 32) {
            float xv = sv[w][p];
            int xi = si[w][p];
            if (xv > bv || (xv == bv && xi < bi)) { bv = xv; bi = xi; bp = p; }
        }
        float wv = bv; int wi = bi;
#pragma unroll
        for (int o = 16; o; o >>= 1) {
            float ov = __shfl_xor_sync(0xffffffffu, wv, o);
            int   oi = __shfl_xor_sync(0xffffffffu, wi, o);
            if (ov > wv || (ov == wv && oi < wi)) { wv = ov; wi = oi; }
        }
        if (lane == 0) g_knn[b][n][r] = wi;
        if (bv == wv && bi == wi && bp >= 0) sv[w][bp] = NEG_INF;
        __syncwarp();
    }
}

// ---------------- U = f*W1^T, V = f*(W2-W1)^T + b ----------------
template <int C>
__global__ void uv_gemm(const float* __restrict__ f, long long bs, int rs,
                        const float* __restrict__ w, const float* __restrict__ bias) {
    constexpr int KT = (C < 32) ? C : 32;
    __shared__ float sF[KT][68];
    __shared__ float sW1[KT][68];
    __shared__ float sDW[KT][68];
    int b = blockIdx.y;
    int n0 = blockIdx.x * 64;
    int o0 = blockIdx.z * 64;
    int tx = threadIdx.x, ty = threadIdx.y;
    int tid = ty * 16 + tx;
    const float* fb = f + (long long)b * bs;
    float au[4][4], av[4][4];
#pragma unroll
    for (int i = 0; i < 4; ++i)
#pragma unroll
        for (int j = 0; j < 4; ++j) { au[i][j] = 0.f; av[i][j] = 0.f; }

    for (int k0 = 0; k0 < C; k0 += KT) {
        for (int t = tid; t < 64 * KT; t += 256) {
            int r = t / KT, c = t - r * KT;
            sF[c][r] = fb[(long long)(n0 + r) * rs + k0 + c];
            float w1 = w[(o0 + r) * 2 * C + k0 + c];
            float w2 = w[(o0 + r) * 2 * C + C + k0 + c];
            sW1[c][r] = w1; sDW[c][r] = w2 - w1;
        }
        __syncthreads();
#pragma unroll
        for (int c = 0; c < KT; ++c) {
            float4 f4 = *(const float4*)&sF[c][ty * 4];
            float4 w4 = *(const float4*)&sW1[c][tx * 4];
            float4 d4 = *(const float4*)&sDW[c][tx * 4];
            float a[4] = {f4.x, f4.y, f4.z, f4.w};
            float wv[4] = {w4.x, w4.y, w4.z, w4.w};
            float dv[4] = {d4.x, d4.y, d4.z, d4.w};
#pragma unroll
            for (int i = 0; i < 4; ++i)
#pragma unroll
                for (int j = 0; j < 4; ++j) {
                    au[i][j] += a[i] * wv[j];
                    av[i][j] += a[i] * dv[j];
                }
        }
        __syncthreads();
    }
    float bb0 = bias[o0 + tx * 4 + 0];
    float bb1 = bias[o0 + tx * 4 + 1];
    float bb2 = bias[o0 + tx * 4 + 2];
    float bb3 = bias[o0 + tx * 4 + 3];
#pragma unroll
    for (int i = 0; i < 4; ++i) {
        int n = n0 + ty * 4 + i;
        float4 u4 = {au[i][0], au[i][1], au[i][2], au[i][3]};
        float4 v4 = {av[i][0] + bb0, av[i][1] + bb1, av[i][2] + bb2, av[i][3] + bb3};
        *(float4*)&g_U[b][n][o0 + tx * 4] = u4;
        *(float4*)&g_V[b][n][o0 + tx * 4] = v4;
    }
}

// ---------------- gather + k-max/min + GN stats ----------------
template <int O, int P>
__global__ void gather_reduce() {
    constexpr int PY = 256 / O;
    __shared__ int sidx[P][KNN];
    __shared__ float red[256];
    int o = threadIdx.x, py = threadIdx.y;
    int t = py * O + o;
    int b = blockIdx.y, n0 = blockIdx.x * P;
    for (int j = t; j < P * KNN; j += 256)
        sidx[j / KNN][j % KNN] = g_knn[b][n0 + j / KNN][j % KNN];
    __syncthreads();
    float ts1 = 0.f, ts2 = 0.f;
    for (int p = py; p < P; p += PY) {
        int n = n0 + p;
        float v = g_V[b][n][o];
        float mx = NEG_INF, mn = POS_INF;
#pragma unroll
        for (int k = 0; k < KNN; ++k) {
            float y = g_U[b][sidx[p][k]][o] + v;
            mx = fmaxf(mx, y); mn = fminf(mn, y);
            ts1 += y; ts2 += y * y;
        }
        g_maxv[b][n][o] = mx;
        g_minv[b][n][o] = mn;
    }
    red[t] = ts1; __syncthreads();
    if (t < NG) {
        float s = 0.f;
        for (int pp = 0; pp < PY; ++pp)
            for (int i = 0; i < O / NG; ++i) s += red[pp * O + t * (O / NG) + i];
        atomicAdd(&g_ssum[b * NG + t], s);
    }
    __syncthreads();
    red[t] = ts2; __syncthreads();
    if (t < NG) {
        float s = 0.f;
        for (int pp = 0; pp < PY; ++pp)
            for (int i = 0; i < O / NG; ++i) s += red[pp * O + t * (O / NG) + i];
        atomicAdd(&g_ssq[b * NG + t], s);
    }
}

// ---------------- GN + lrelu applied to k-extremum ----------------
template <int O>
__global__ void apply_kernel(const float* __restrict__ gamma, const float* __restrict__ beta, int col0) {
    int l = blockIdx.x * blockDim.x + threadIdx.x;
    int o = l % O;
    int n = (l / O) % NPTS;
    int b = l / (O * NPTS);
    int g = o / (O / NG);
    float cnt = (float)(O / NG) * NPTS * KNN;
    float mean = g_ssum[b * NG + g] / cnt;
    float var = fmaxf(g_ssq[b * NG + g] / cnt - mean * mean, 0.f);
    float inv = rsqrtf(var + EPSV);
    float s = gamma[o] * inv;
    float tt = beta[o] - mean * s;
    float sel = (s >= 0.f) ? g_maxv[b][n][o] : g_minv[b][n][o];
    float yv = s * sel + tt;
    g_res[b][n][col0 + o] = (yv >= 0.f) ? yv : 0.2f * yv;
}

// ---------------- w3 pointwise GEMM ----------------
__global__ void w3_gemm(const float* __restrict__ w3, const float* __restrict__ b3) {
    __shared__ float sW[32][68];
    __shared__ float sR[32][68];
    int b = blockIdx.z;
    int o0 = blockIdx.y * 64, n0 = blockIdx.x * 64;
    int tx = threadIdx.x, ty = threadIdx.y;
    int tid = ty * 16 + tx;
    float acc[4][4];
#pragma unroll
    for (int i = 0; i < 4; ++i)
#pragma unroll
        for (int j = 0; j < 4; ++j) acc[i][j] = 0.f;

    for (int k0 = 0; k0 < 256; k0 += 32) {
        for (int t = tid; t < 64 * 32; t += 256) {
            int r = t >> 5, c = t & 31;
            sW[c][r] = w3[(o0 + r) * 256 + k0 + c];
            sR[c][r] = g_res[b][n0 + r][k0 + c];
        }
        __syncthreads();
#pragma unroll
        for (int c = 0; c < 32; ++c) {
            float4 a4 = *(const float4*)&sW[c][ty * 4];
            float4 b4 = *(const float4*)&sR[c][tx * 4];
            float a[4] = {a4.x, a4.y, a4.z, a4.w};
            float bv[4] = {b4.x, b4.y, b4.z, b4.w};
#pragma unroll
            for (int i = 0; i < 4; ++i)
#pragma unroll
                for (int j = 0; j < 4; ++j) acc[i][j] += a[i] * bv[j];
        }
        __syncthreads();
    }
#pragma unroll
    for (int i = 0; i < 4; ++i) {
        int o = o0 + ty * 4 + i;
        float bv = b3[o];
        float4 o4 = {acc[i][0] + bv, acc[i][1] + bv, acc[i][2] + bv, acc[i][3] + bv};
        *(float4*)&g_z[b][o][n0 + tx * 4] = o4;
    }
}

// ---------------- stats of z per (b, group) ----------------
__global__ void stats3_kernel() {
    int b = blockIdx.x / NG, g = blockIdx.x % NG;
    int tid = threadIdx.x;
    float s1 = 0.f, s2 = 0.f;
    for (int i = tid; i < 32 * NPTS; i += 256) {
        int o = g * 32 + (i >> 11);
        int n = i & (NPTS - 1);
        float v = g_z[b][o][n];
        s1 += v; s2 += v * v;
    }
    __shared__ float r1[256], r2[256];
    r1[tid] = s1; r2[tid] = s2; __syncthreads();
    for (int st = 128; st; st >>= 1) {
        if (tid < st) { r1[tid] += r1[tid + st]; r2[tid] += r2[tid + st]; }
        __syncthreads();
    }
    if (tid == 0) { g_ssum[b * NG + g] = r1[0]; g_ssq[b * NG + g] = r2[0]; }
}

// ---------------- GN+lrelu+global max/mean pooling ----------------
__global__ void pool_kernel(const float* __restrict__ g3, const float* __restrict__ h3) {
    int b = blockIdx.x >> 8, o = blockIdx.x & 255;
    int g = o >> 5;
    float cnt = 32.f * NPTS;
    float mean = g_ssum[b * NG + g] / cnt;
    float var = fmaxf(g_ssq[b * NG + g] / cnt - mean * mean, 0.f);
    float inv = rsqrtf(var + EPSV);
    float s = g3[o] * inv;
    float tt = h3[o] - mean * s;
    int tid = threadIdx.x;
    float mx = NEG_INF, sum = 0.f;
    for (int n = tid; n < NPTS; n += 256) {
        float v = s * g_z[b][o][n] + tt;
        v = (v >= 0.f) ? v : 0.2f * v;
        mx = fmaxf(mx, v); sum += v;
    }
    __shared__ float rm[256], rs_[256];
    rm[tid] = mx; rs_[tid] = sum; __syncthreads();
    for (int st = 128; st; st >>= 1) {
        if (tid < st) { rm[tid] = fmaxf(rm[tid], rm[tid + st]); rs_[tid] += rs_[tid + st]; }
        __syncthreads();
    }
    if (tid == 0) { g_pool[b][o] = rm[0]; g_pool[b][256 + o] = rs_[0] / (float)NPTS; }
}

// ---------------- FC head ----------------
__global__ void head_kernel(const float* __restrict__ fw0, const float* __restrict__ fb0,
                            const float* __restrict__ fw1, const float* __restrict__ fb1,
                            const float* __restrict__ fw2, const float* __restrict__ fb2,
                            float* __restrict__ out) {
    __shared__ float sv[512];
    int b = blockIdx.x, t = threadIdx.x;
    sv[t] = g_pool[b][t];
    __syncthreads();
    float acc = fb0[t];
    {
        const float4* w4 = (const float4*)(fw0 + t * 512);
        const float4* v4 = (const float4*)sv;
        for (int c4 = 0; c4 < 128; ++c4) {
            float4 w = w4[c4]; float4 v = v4[c4];
            acc += w.x * v.x + w.y * v.y + w.z * v.z + w.w * v.w;
        }
    }
    acc = (acc >= 0.f) ? acc : 0.2f * acc;
    __syncthreads(); sv[t] = acc; __syncthreads();
    acc = fb1[t];
    {
        const float4* w4 = (const float4*)(fw1 + t * 512);
        const float4* v4 = (const float4*)sv;
        for (int c4 = 0; c4 < 128; ++c4) {
            float4 w = w4[c4]; float4 v = v4[c4];
            acc += w.x * v.x + w.y * v.y + w.z * v.z + w.w * v.w;
        }
    }
    acc = (acc >= 0.f) ? acc : 0.2f * acc;
    __syncthreads(); sv[t] = acc; __syncthreads();
    if (t < 256) {
        float a2 = fb2[t];
        const float4* w4 = (const float4*)(fw2 + t * 512);
        const float4* v4 = (const float4*)sv;
        for (int c4 = 0; c4 < 128; ++c4) {
            float4 w = w4[c4]; float4 v = v4[c4];
            a2 += w.x * v.x + w.y * v.y + w.z * v.z + w.w * v.w;
        }
        out[b * 256 + t] = a2;
    }
}

extern "C" void kernel_launch(void* const* d_in, const int* in_sizes, int n_in,
                              void* d_out, int out_size) {
    const float* x  = (const float*)d_in[0];
    const float* w0 = (const float*)d_in[1];
    const float* b0 = (const float*)d_in[2];
    const float* g0 = (const float*)d_in[3];
    const float* h0 = (const float*)d_in[4];
    const float* w1 = (const float*)d_in[5];
    const float* b1 = (const float*)d_in[6];
    const float* g1 = (const float*)d_in[7];
    const float* h1 = (const float*)d_in[8];
    const float* w2 = (const float*)d_in[9];
    const float* b2 = (const float*)d_in[10];
    const float* g2 = (const float*)d_in[11];
    const float* h2 = (const float*)d_in[12];
    const float* w3 = (const float*)d_in[13];
    const float* b3 = (const float*)d_in[14];
    const float* g3 = (const float*)d_in[15];
    const float* h3 = (const float*)d_in[16];
    const float* fw0 = (const float*)d_in[17];
    const float* fb0 = (const float*)d_in[18];
    const float* fw1 = (const float*)d_in[19];
    const float* fb1 = (const float*)d_in[20];
    const float* fw2 = (const float*)d_in[21];
    const float* fb2 = (const float*)d_in[22];
    float* out = (float*)d_out;

    float* resp = nullptr;
    cudaGetSymbolAddress((void**)&resp, g_res);

    dim3 blk16(16, 16);
    dim3 pd128grid(NPTS / 128, NPTS / 128, BB);

    // ---------- stage 1: C=3 -> O=64, res cols [0,64) ----------
    {
        long long bs = (long long)NPTS * 3;
        xx_kernel<<<BB * NPTS / 8, 256>>>(x, bs, 3, 3);
        pd_kernel<3><<<dim3(NPTS / 64, NPTS / 64, BB), blk16>>>(x, bs, 3);
        topk_kernel<<<BB * NPTS / 4, 128>>>();
        uv_gemm<3><<<dim3(NPTS / 64, BB, 1), blk16>>>(x, bs, 3, w0, b0);
        gather_reduce<64, 16><<<dim3(NPTS / 16, BB), dim3(64, 4)>>>();
        apply_kernel<64><<<BB * NPTS * 64 / 256, 256>>>(g0, h0, 0);
    }
    // ---------- stage 2: C=64 (cols 0..63) -> O=64, res cols [64,128) ----------
    {
        long long bs = (long long)NPTS * 256;
        xx_kernel<<<BB * NPTS / 8, 256>>>(resp, bs, 256, 64);
        pd_kernel128<<<pd128grid, blk16>>>(resp, bs, 256);
        topk_kernel<<<BB * NPTS / 4, 128>>>();
        uv_gemm<64><<<dim3(NPTS / 64, BB, 1), blk16>>>(resp, bs, 256, w1, b1);
        gather_reduce<64, 16><<<dim3(NPTS / 16, BB), dim3(64, 4)>>>();
        apply_kernel<64><<<BB * NPTS * 64 / 256, 256>>>(g1, h1, 64);
    }
    // ---------- stage 3: C=64 (cols 64..127) -> O=128, res cols [128,256) ----------
    {
        long long bs = (long long)NPTS * 256;
        const float* f = resp + 64;
        xx_kernel<<<BB * NPTS / 8, 256>>>(f, bs, 256, 64);
        pd_kernel128<<<pd128grid, blk16>>>(f, bs, 256);
        topk_kernel<<<BB * NPTS / 4, 128>>>();
        uv_gemm<64><<<dim3(NPTS / 64, BB, 2), blk16>>>(f, bs, 256, w2, b2);
        gather_reduce<128, 8><<<dim3(NPTS / 8, BB), dim3(128, 2)>>>();
        apply_kernel<128><<<BB * NPTS * 128 / 256, 256>>>(g2, h2, 128);
    }
    // ---------- w3 pointwise + GN + pool + head ----------
    w3_gemm<<<dim3(NPTS / 64, 256 / 64, BB), blk16>>>(w3, b3);
    stats3_kernel<<<BB * NG, 256>>>();
    pool_kernel<<<BB * 256, 256>>>(g3, h3);
    head_kernel<<<BB, 512>>>(fw0, fb0, fw1, fb1, fw2, fb2, out);
}

// round 4
// speedup vs baseline: 2.1113x; 1.1272x over previous
#include <cuda_runtime.h>

#define BB 8
#define NPTS 2048
#define KNN 20
#define NG 8
#define EPSV 1e-5f

#define NEG_INF __int_as_float(0xff800000)
#define POS_INF __int_as_float(0x7f800000)

// ---------------- device scratch ----------------
__device__ float g_pd[BB][NPTS][NPTS];
__device__ float g_xx[BB][NPTS];
__device__ int   g_knn[BB][NPTS][KNN];
__device__ float g_res[BB][NPTS][256];
__device__ float g_U[BB][NPTS][128];
__device__ float g_V[BB][NPTS][128];
__device__ float g_maxv[BB][NPTS][128];
__device__ float g_minv[BB][NPTS][128];
__device__ float g_z[BB][256][NPTS];
__device__ float g_ssum[BB * NG];
__device__ float g_ssq[BB * NG];
__device__ float g_pool[BB][512];

// ---------------- xx = sum_c f^2 (+ zero the stage stats) ----------------
__global__ void xx_kernel(const float* __restrict__ f, long long bs, int rs, int C) {
    if (blockIdx.x == 0 && threadIdx.x < BB * NG) {
        g_ssum[threadIdx.x] = 0.f; g_ssq[threadIdx.x] = 0.f;
    }
    int row = blockIdx.x * 8 + (threadIdx.x >> 5);
    int lane = threadIdx.x & 31;
    int b = row / NPTS, n = row % NPTS;
    const float* p = f + (long long)b * bs + (long long)n * rs;
    float s = 0.f;
    for (int c = lane; c < C; c += 32) { float v = p[c]; s += v * v; }
#pragma unroll
    for (int o = 16; o; o >>= 1) s += __shfl_xor_sync(0xffffffffu, s, o);
    if (lane == 0) g_xx[b][n] = s;
}

// ---------------- pd (C=3 path): 64x64 tile ----------------
template <int C>
__global__ void pd_kernel(const float* __restrict__ f, long long bs, int rs) {
    constexpr int KT = (C < 32) ? C : 32;
    __shared__ float sA[KT][68];
    __shared__ float sB[KT][68];
    int b = blockIdx.z;
    int n0 = blockIdx.y * 64, m0 = blockIdx.x * 64;
    int tx = threadIdx.x, ty = threadIdx.y;
    int tid = ty * 16 + tx;
    const float* fb = f + (long long)b * bs;
    float acc[4][4];
#pragma unroll
    for (int i = 0; i < 4; ++i)
#pragma unroll
        for (int j = 0; j < 4; ++j) acc[i][j] = 0.f;

    for (int k0 = 0; k0 < C; k0 += KT) {
        for (int t = tid; t < 64 * KT; t += 256) {
            int r = t / KT, c = t - r * KT;
            sA[c][r] = fb[(long long)(n0 + r) * rs + k0 + c];
            sB[c][r] = fb[(long long)(m0 + r) * rs + k0 + c];
        }
        __syncthreads();
#pragma unroll
        for (int c = 0; c < KT; ++c) {
            float4 a4 = *(const float4*)&sA[c][ty * 4];
            float4 b4 = *(const float4*)&sB[c][tx * 4];
            float a[4] = {a4.x, a4.y, a4.z, a4.w};
            float bv[4] = {b4.x, b4.y, b4.z, b4.w};
#pragma unroll
            for (int i = 0; i < 4; ++i)
#pragma unroll
                for (int j = 0; j < 4; ++j) acc[i][j] += a[i] * bv[j];
        }
        __syncthreads();
    }
    float xn[4], xm[4];
#pragma unroll
    for (int i = 0; i < 4; ++i) xn[i] = g_xx[b][n0 + ty * 4 + i];
#pragma unroll
    for (int j = 0; j < 4; ++j) xm[j] = g_xx[b][m0 + tx * 4 + j];
#pragma unroll
    for (int i = 0; i < 4; ++i) {
        float4 o4;
        o4.x = -(xn[i] - 2.f * acc[i][0] + xm[0]);
        o4.y = -(xn[i] - 2.f * acc[i][1] + xm[1]);
        o4.z = -(xn[i] - 2.f * acc[i][2] + xm[2]);
        o4.w = -(xn[i] - 2.f * acc[i][3] + xm[3]);
        __stcs((float4*)&g_pd[b][n0 + ty * 4 + i][m0 + tx * 4], o4);
    }
}

// ---------------- pd (C=64 path): 128x128 tile, 8x8 per thread ----------------
__global__ void __launch_bounds__(256) pd_kernel128(const float* __restrict__ f, long long bs, int rs) {
    __shared__ float sA[32][132];
    __shared__ float sB[32][132];
    int b = blockIdx.z;
    int n0 = blockIdx.y * 128, m0 = blockIdx.x * 128;
    int tx = threadIdx.x, ty = threadIdx.y;
    int tid = ty * 16 + tx;
    const float* fb = f + (long long)b * bs;
    float acc[8][8];
#pragma unroll
    for (int i = 0; i < 8; ++i)
#pragma unroll
        for (int j = 0; j < 8; ++j) acc[i][j] = 0.f;

    for (int k0 = 0; k0 < 64; k0 += 32) {
        for (int t = tid; t < 128 * 32; t += 256) {
            int r = t >> 5, c = t & 31;
            sA[c][r] = fb[(long long)(n0 + r) * rs + k0 + c];
            sB[c][r] = fb[(long long)(m0 + r) * rs + k0 + c];
        }
        __syncthreads();
#pragma unroll
        for (int c = 0; c < 32; ++c) {
            float4 a0 = *(const float4*)&sA[c][ty * 8];
            float4 a1 = *(const float4*)&sA[c][ty * 8 + 4];
            float4 b0 = *(const float4*)&sB[c][tx * 8];
            float4 b1 = *(const float4*)&sB[c][tx * 8 + 4];
            float a[8] = {a0.x, a0.y, a0.z, a0.w, a1.x, a1.y, a1.z, a1.w};
            float bv[8] = {b0.x, b0.y, b0.z, b0.w, b1.x, b1.y, b1.z, b1.w};
#pragma unroll
            for (int i = 0; i < 8; ++i)
#pragma unroll
                for (int j = 0; j < 8; ++j) acc[i][j] += a[i] * bv[j];
        }
        __syncthreads();
    }
    float xn[8], xm[8];
#pragma unroll
    for (int i = 0; i < 8; ++i) xn[i] = g_xx[b][n0 + ty * 8 + i];
#pragma unroll
    for (int j = 0; j < 8; ++j) xm[j] = g_xx[b][m0 + tx * 8 + j];
#pragma unroll
    for (int i = 0; i < 8; ++i) {
        int n = n0 + ty * 8 + i;
        float4 o4;
        o4.x = -(xn[i] - 2.f * acc[i][0] + xm[0]);
        o4.y = -(xn[i] - 2.f * acc[i][1] + xm[1]);
        o4.z = -(xn[i] - 2.f * acc[i][2] + xm[2]);
        o4.w = -(xn[i] - 2.f * acc[i][3] + xm[3]);
        __stcs((float4*)&g_pd[b][n][m0 + tx * 8], o4);
        o4.x = -(xn[i] - 2.f * acc[i][4] + xm[4]);
        o4.y = -(xn[i] - 2.f * acc[i][5] + xm[5]);
        o4.z = -(xn[i] - 2.f * acc[i][6] + xm[6]);
        o4.w = -(xn[i] - 2.f * acc[i][7] + xm[7]);
        __stcs((float4*)&g_pd[b][n][m0 + tx * 8 + 4], o4);
    }
}

// ---------------- exact top-K SET per row: fill-first + warp threshold + replace-min ----------------
__global__ void topk_kernel() {
    __shared__ float sv[4][640];
    __shared__ int   si[4][640];
    __shared__ int   scnt[4];
    int w = threadIdx.x >> 5, lane = threadIdx.x & 31;
    int row = blockIdx.x * 4 + w;
    int b = row / NPTS, n = row % NPTS;
    const float4* pr4 = (const float4*)&g_pd[b][n][0];

    float v[KNN]; int idl[KNN];
    // fill phase: first 5 float4 iterations = exactly 20 elements per lane, no scans
#pragma unroll
    for (int it = 0; it < 5; ++it) {
        int i = lane + it * 32;
        float4 x4 = __ldcs(&pr4[i]);
        v[it * 4 + 0] = x4.x; idl[it * 4 + 0] = 4 * i + 0;
        v[it * 4 + 1] = x4.y; idl[it * 4 + 1] = 4 * i + 1;
        v[it * 4 + 2] = x4.z; idl[it * 4 + 2] = 4 * i + 2;
        v[it * 4 + 3] = x4.w; idl[it * 4 + 3] = 4 * i + 3;
    }
    float lmin = v[0]; int lslot = 0;
#pragma unroll
    for (int j = 1; j < KNN; ++j)
        if (v[j] < lmin) { lmin = v[j]; lslot = j; }
    float T = lmin;
#pragma unroll
    for (int o = 16; o; o >>= 1) T = fmaxf(T, __shfl_xor_sync(0xffffffffu, T, o));

    for (int i = lane + 5 * 32; i < NPTS / 4; i += 32) {
        float4 x4 = __ldcs(&pr4[i]);
        float xs[4] = {x4.x, x4.y, x4.z, x4.w};
#pragma unroll
        for (int q = 0; q < 4; ++q) {
            float x = xs[q];
            if (x >= T && x > lmin) {
                v[lslot] = x; idl[lslot] = i * 4 + q;
                lmin = v[0]; lslot = 0;
#pragma unroll
                for (int j = 1; j < KNN; ++j)
                    if (v[j] < lmin) { lmin = v[j]; lslot = j; }
            }
        }
        float t = lmin;
#pragma unroll
        for (int o = 16; o; o >>= 1) t = fmaxf(t, __shfl_xor_sync(0xffffffffu, t, o));
        T = t;
    }

    // compact survivors (>= T) to shared
    if (lane == 0) scnt[w] = 0;
    __syncwarp();
#pragma unroll
    for (int j = 0; j < KNN; ++j) {
        if (v[j] >= T) {
            int p = atomicAdd(&scnt[w], 1);
            sv[w][p] = v[j]; si[w][p] = idl[j];
        }
    }
    __syncwarp();
    int cnt = scnt[w];

    // extract top-20 by repeated warp argmax (value desc, index asc)
    for (int r = 0; r < KNN; ++r) {
        float bv = NEG_INF; int bi = 0x7fffffff; int bp = -1;
        for (int p = lane; p < cnt; p += 32) {
            float xv = sv[w][p];
            int xi = si[w][p];
            if (xv > bv || (xv == bv && xi < bi)) { bv = xv; bi = xi; bp = p; }
        }
        float wv = bv; int wi = bi;
#pragma unroll
        for (int o = 16; o; o >>= 1) {
            float ov = __shfl_xor_sync(0xffffffffu, wv, o);
            int   oi = __shfl_xor_sync(0xffffffffu, wi, o);
            if (ov > wv || (ov == wv && oi < wi)) { wv = ov; wi = oi; }
        }
        if (lane == 0) g_knn[b][n][r] = wi;
        if (bv == wv && bi == wi && bp >= 0) sv[w][bp] = NEG_INF;
        __syncwarp();
    }
}

// ---------------- U = f*W1^T, V = f*(W2-W1)^T + b ----------------
template <int C>
__global__ void uv_gemm(const float* __restrict__ f, long long bs, int rs,
                        const float* __restrict__ w, const float* __restrict__ bias) {
    constexpr int KT = (C < 32) ? C : 32;
    __shared__ float sF[KT][68];
    __shared__ float sW1[KT][68];
    __shared__ float sDW[KT][68];
    int b = blockIdx.y;
    int n0 = blockIdx.x * 64;
    int o0 = blockIdx.z * 64;
    int tx = threadIdx.x, ty = threadIdx.y;
    int tid = ty * 16 + tx;
    const float* fb = f + (long long)b * bs;
    float au[4][4], av[4][4];
#pragma unroll
    for (int i = 0; i < 4; ++i)
#pragma unroll
        for (int j = 0; j < 4; ++j) { au[i][j] = 0.f; av[i][j] = 0.f; }

    for (int k0 = 0; k0 < C; k0 += KT) {
        for (int t = tid; t < 64 * KT; t += 256) {
            int r = t / KT, c = t - r * KT;
            sF[c][r] = fb[(long long)(n0 + r) * rs + k0 + c];
            float w1 = w[(o0 + r) * 2 * C + k0 + c];
            float w2 = w[(o0 + r) * 2 * C + C + k0 + c];
            sW1[c][r] = w1; sDW[c][r] = w2 - w1;
        }
        __syncthreads();
#pragma unroll
        for (int c = 0; c < KT; ++c) {
            float4 f4 = *(const float4*)&sF[c][ty * 4];
            float4 w4 = *(const float4*)&sW1[c][tx * 4];
            float4 d4 = *(const float4*)&sDW[c][tx * 4];
            float a[4] = {f4.x, f4.y, f4.z, f4.w};
            float wv[4] = {w4.x, w4.y, w4.z, w4.w};
            float dv[4] = {d4.x, d4.y, d4.z, d4.w};
#pragma unroll
            for (int i = 0; i < 4; ++i)
#pragma unroll
                for (int j = 0; j < 4; ++j) {
                    au[i][j] += a[i] * wv[j];
                    av[i][j] += a[i] * dv[j];
                }
        }
        __syncthreads();
    }
    float bb0 = bias[o0 + tx * 4 + 0];
    float bb1 = bias[o0 + tx * 4 + 1];
    float bb2 = bias[o0 + tx * 4 + 2];
    float bb3 = bias[o0 + tx * 4 + 3];
#pragma unroll
    for (int i = 0; i < 4; ++i) {
        int n = n0 + ty * 4 + i;
        float4 u4 = {au[i][0], au[i][1], au[i][2], au[i][3]};
        float4 v4 = {av[i][0] + bb0, av[i][1] + bb1, av[i][2] + bb2, av[i][3] + bb3};
        *(float4*)&g_U[b][n][o0 + tx * 4] = u4;
        *(float4*)&g_V[b][n][o0 + tx * 4] = v4;
    }
}

// ---------------- gather + k-max/min + GN stats ----------------
template <int O, int P>
__global__ void gather_reduce() {
    constexpr int PY = 256 / O;
    __shared__ int sidx[P][KNN];
    __shared__ float red[256];
    int o = threadIdx.x, py = threadIdx.y;
    int t = py * O + o;
    int b = blockIdx.y, n0 = blockIdx.x * P;
    for (int j = t; j < P * KNN; j += 256)
        sidx[j / KNN][j % KNN] = g_knn[b][n0 + j / KNN][j % KNN];
    __syncthreads();
    float ts1 = 0.f, ts2 = 0.f;
    for (int p = py; p < P; p += PY) {
        int n = n0 + p;
        float v = g_V[b][n][o];
        float mx = NEG_INF, mn = POS_INF;
#pragma unroll
        for (int k = 0; k < KNN; ++k) {
            float y = g_U[b][sidx[p][k]][o] + v;
            mx = fmaxf(mx, y); mn = fminf(mn, y);
            ts1 += y; ts2 += y * y;
        }
        g_maxv[b][n][o] = mx;
        g_minv[b][n][o] = mn;
    }
    red[t] = ts1; __syncthreads();
    if (t < NG) {
        float s = 0.f;
        for (int pp = 0; pp < PY; ++pp)
            for (int i = 0; i < O / NG; ++i) s += red[pp * O + t * (O / NG) + i];
        atomicAdd(&g_ssum[b * NG + t], s);
    }
    __syncthreads();
    red[t] = ts2; __syncthreads();
    if (t < NG) {
        float s = 0.f;
        for (int pp = 0; pp < PY; ++pp)
            for (int i = 0; i < O / NG; ++i) s += red[pp * O + t * (O / NG) + i];
        atomicAdd(&g_ssq[b * NG + t], s);
    }
}

// ---------------- GN + lrelu applied to k-extremum ----------------
template <int O>
__global__ void apply_kernel(const float* __restrict__ gamma, const float* __restrict__ beta, int col0) {
    int l = blockIdx.x * blockDim.x + threadIdx.x;
    int o = l % O;
    int n = (l / O) % NPTS;
    int b = l / (O * NPTS);
    int g = o / (O / NG);
    float cnt = (float)(O / NG) * NPTS * KNN;
    float mean = g_ssum[b * NG + g] / cnt;
    float var = fmaxf(g_ssq[b * NG + g] / cnt - mean * mean, 0.f);
    float inv = rsqrtf(var + EPSV);
    float s = gamma[o] * inv;
    float tt = beta[o] - mean * s;
    float sel = (s >= 0.f) ? g_maxv[b][n][o] : g_minv[b][n][o];
    float yv = s * sel + tt;
    g_res[b][n][col0 + o] = (yv >= 0.f) ? yv : 0.2f * yv;
}

// ---------------- w3 pointwise GEMM: 128x128 tile, 8x8 per thread ----------------
__global__ void __launch_bounds__(256) w3_gemm128(const float* __restrict__ w3, const float* __restrict__ b3) {
    __shared__ float sW[32][132];
    __shared__ float sR[32][132];
    int b = blockIdx.z;
    int o0 = blockIdx.y * 128, n0 = blockIdx.x * 128;
    int tx = threadIdx.x, ty = threadIdx.y;
    int tid = ty * 16 + tx;
    float acc[8][8];
#pragma unroll
    for (int i = 0; i < 8; ++i)
#pragma unroll
        for (int j = 0; j < 8; ++j) acc[i][j] = 0.f;

    for (int k0 = 0; k0 < 256; k0 += 32) {
        for (int t = tid; t < 128 * 32; t += 256) {
            int r = t >> 5, c = t & 31;
            sW[c][r] = w3[(o0 + r) * 256 + k0 + c];
            sR[c][r] = g_res[b][n0 + r][k0 + c];
        }
        __syncthreads();
#pragma unroll
        for (int c = 0; c < 32; ++c) {
            float4 a0 = *(const float4*)&sW[c][ty * 8];
            float4 a1 = *(const float4*)&sW[c][ty * 8 + 4];
            float4 b0 = *(const float4*)&sR[c][tx * 8];
            float4 b1 = *(const float4*)&sR[c][tx * 8 + 4];
            float a[8] = {a0.x, a0.y, a0.z, a0.w, a1.x, a1.y, a1.z, a1.w};
            float bv[8] = {b0.x, b0.y, b0.z, b0.w, b1.x, b1.y, b1.z, b1.w};
#pragma unroll
            for (int i = 0; i < 8; ++i)
#pragma unroll
                for (int j = 0; j < 8; ++j) acc[i][j] += a[i] * bv[j];
        }
        __syncthreads();
    }
#pragma unroll
    for (int i = 0; i < 8; ++i) {
        int o = o0 + ty * 8 + i;
        float bv = b3[o];
        float4 o4;
        o4.x = acc[i][0] + bv; o4.y = acc[i][1] + bv;
        o4.z = acc[i][2] + bv; o4.w = acc[i][3] + bv;
        *(float4*)&g_z[b][o][n0 + tx * 8] = o4;
        o4.x = acc[i][4] + bv; o4.y = acc[i][5] + bv;
        o4.z = acc[i][6] + bv; o4.w = acc[i][7] + bv;
        *(float4*)&g_z[b][o][n0 + tx * 8 + 4] = o4;
    }
}

// ---------------- stats of z per (b, group) ----------------
__global__ void stats3_kernel() {
    int b = blockIdx.x / NG, g = blockIdx.x % NG;
    int tid = threadIdx.x;
    float s1 = 0.f, s2 = 0.f;
    for (int i = tid; i < 32 * NPTS; i += 256) {
        int o = g * 32 + (i >> 11);
        int n = i & (NPTS - 1);
        float v = g_z[b][o][n];
        s1 += v; s2 += v * v;
    }
    __shared__ float r1[256], r2[256];
    r1[tid] = s1; r2[tid] = s2; __syncthreads();
    for (int st = 128; st; st >>= 1) {
        if (tid < st) { r1[tid] += r1[tid + st]; r2[tid] += r2[tid + st]; }
        __syncthreads();
    }
    if (tid == 0) { g_ssum[b * NG + g] = r1[0]; g_ssq[b * NG + g] = r2[0]; }
}

// ---------------- GN+lrelu+global max/mean pooling ----------------
__global__ void pool_kernel(const float* __restrict__ g3, const float* __restrict__ h3) {
    int b = blockIdx.x >> 8, o = blockIdx.x & 255;
    int g = o >> 5;
    float cnt = 32.f * NPTS;
    float mean = g_ssum[b * NG + g] / cnt;
    float var = fmaxf(g_ssq[b * NG + g] / cnt - mean * mean, 0.f);
    float inv = rsqrtf(var + EPSV);
    float s = g3[o] * inv;
    float tt = h3[o] - mean * s;
    int tid = threadIdx.x;
    float mx = NEG_INF, sum = 0.f;
    for (int n = tid; n < NPTS; n += 256) {
        float v = s * g_z[b][o][n] + tt;
        v = (v >= 0.f) ? v : 0.2f * v;
        mx = fmaxf(mx, v); sum += v;
    }
    __shared__ float rm[256], rs_[256];
    rm[tid] = mx; rs_[tid] = sum; __syncthreads();
    for (int st = 128; st; st >>= 1) {
        if (tid < st) { rm[tid] = fmaxf(rm[tid], rm[tid + st]); rs_[tid] += rs_[tid + st]; }
        __syncthreads();
    }
    if (tid == 0) { g_pool[b][o] = rm[0]; g_pool[b][256 + o] = rs_[0] / (float)NPTS; }
}

// ---------------- FC head ----------------
__global__ void head_kernel(const float* __restrict__ fw0, const float* __restrict__ fb0,
                            const float* __restrict__ fw1, const float* __restrict__ fb1,
                            const float* __restrict__ fw2, const float* __restrict__ fb2,
                            float* __restrict__ out) {
    __shared__ float sv[512];
    int b = blockIdx.x, t = threadIdx.x;
    sv[t] = g_pool[b][t];
    __syncthreads();
    float acc = fb0[t];
    {
        const float4* w4 = (const float4*)(fw0 + t * 512);
        const float4* v4 = (const float4*)sv;
        for (int c4 = 0; c4 < 128; ++c4) {
            float4 w = w4[c4]; float4 v = v4[c4];
            acc += w.x * v.x + w.y * v.y + w.z * v.z + w.w * v.w;
        }
    }
    acc = (acc >= 0.f) ? acc : 0.2f * acc;
    __syncthreads(); sv[t] = acc; __syncthreads();
    acc = fb1[t];
    {
        const float4* w4 = (const float4*)(fw1 + t * 512);
        const float4* v4 = (const float4*)sv;
        for (int c4 = 0; c4 < 128; ++c4) {
            float4 w = w4[c4]; float4 v = v4[c4];
            acc += w.x * v.x + w.y * v.y + w.z * v.z + w.w * v.w;
        }
    }
    acc = (acc >= 0.f) ? acc : 0.2f * acc;
    __syncthreads(); sv[t] = acc; __syncthreads();
    if (t < 256) {
        float a2 = fb2[t];
        const float4* w4 = (const float4*)(fw2 + t * 512);
        const float4* v4 = (const float4*)sv;
        for (int c4 = 0; c4 < 128; ++c4) {
            float4 w = w4[c4]; float4 v = v4[c4];
            a2 += w.x * v.x + w.y * v.y + w.z * v.z + w.w * v.w;
        }
        out[b * 256 + t] = a2;
    }
}

extern "C" void kernel_launch(void* const* d_in, const int* in_sizes, int n_in,
                              void* d_out, int out_size) {
    const float* x  = (const float*)d_in[0];
    const float* w0 = (const float*)d_in[1];
    const float* b0 = (const float*)d_in[2];
    const float* g0 = (const float*)d_in[3];
    const float* h0 = (const float*)d_in[4];
    const float* w1 = (const float*)d_in[5];
    const float* b1 = (const float*)d_in[6];
    const float* g1 = (const float*)d_in[7];
    const float* h1 = (const float*)d_in[8];
    const float* w2 = (const float*)d_in[9];
    const float* b2 = (const float*)d_in[10];
    const float* g2 = (const float*)d_in[11];
    const float* h2 = (const float*)d_in[12];
    const float* w3 = (const float*)d_in[13];
    const float* b3 = (const float*)d_in[14];
    const float* g3 = (const float*)d_in[15];
    const float* h3 = (const float*)d_in[16];
    const float* fw0 = (const float*)d_in[17];
    const float* fb0 = (const float*)d_in[18];
    const float* fw1 = (const float*)d_in[19];
    const float* fb1 = (const float*)d_in[20];
    const float* fw2 = (const float*)d_in[21];
    const float* fb2 = (const float*)d_in[22];
    float* out = (float*)d_out;

    float* resp = nullptr;
    cudaGetSymbolAddress((void**)&resp, g_res);

    dim3 blk16(16, 16);
    dim3 pd128grid(NPTS / 128, NPTS / 128, BB);

    // ---------- stage 1: C=3 -> O=64, res cols [0,64) ----------
    // order: xx(0), uv(1), pd(2), topk(3)  -> ncu captures launch index 3 = topk
    {
        long long bs = (long long)NPTS * 3;
        xx_kernel<<<BB * NPTS / 8, 256>>>(x, bs, 3, 3);
        uv_gemm<3><<<dim3(NPTS / 64, BB, 1), blk16>>>(x, bs, 3, w0, b0);
        pd_kernel<3><<<dim3(NPTS / 64, NPTS / 64, BB), blk16>>>(x, bs, 3);
        topk_kernel<<<BB * NPTS / 4, 128>>>();
        gather_reduce<64, 16><<<dim3(NPTS / 16, BB), dim3(64, 4)>>>();
        apply_kernel<64><<<BB * NPTS * 64 / 256, 256>>>(g0, h0, 0);
    }
    // ---------- stage 2: C=64 (cols 0..63) -> O=64, res cols [64,128) ----------
    {
        long long bs = (long long)NPTS * 256;
        xx_kernel<<<BB * NPTS / 8, 256>>>(resp, bs, 256, 64);
        uv_gemm<64><<<dim3(NPTS / 64, BB, 1), blk16>>>(resp, bs, 256, w1, b1);
        pd_kernel128<<<pd128grid, blk16>>>(resp, bs, 256);
        topk_kernel<<<BB * NPTS / 4, 128>>>();
        gather_reduce<64, 16><<<dim3(NPTS / 16, BB), dim3(64, 4)>>>();
        apply_kernel<64><<<BB * NPTS * 64 / 256, 256>>>(g1, h1, 64);
    }
    // ---------- stage 3: C=64 (cols 64..127) -> O=128, res cols [128,256) ----------
    {
        long long bs = (long long)NPTS * 256;
        const float* f = resp + 64;
        xx_kernel<<<BB * NPTS / 8, 256>>>(f, bs, 256, 64);
        uv_gemm<64><<<dim3(NPTS / 64, BB, 2), blk16>>>(f, bs, 256, w2, b2);
        pd_kernel128<<<pd128grid, blk16>>>(f, bs, 256);
        topk_kernel<<<BB * NPTS / 4, 128>>>();
        gather_reduce<128, 8><<<dim3(NPTS / 8, BB), dim3(128, 2)>>>();
        apply_kernel<128><<<BB * NPTS * 128 / 256, 256>>>(g2, h2, 128);
    }
    // ---------- w3 pointwise + GN + pool + head ----------
    w3_gemm128<<<dim3(NPTS / 128, 256 / 128, BB), blk16>>>(w3, b3);
    stats3_kernel<<<BB * NG, 256>>>();
    pool_kernel<<<BB * 256, 256>>>(g3, h3);
    head_kernel<<<BB, 512>>>(fw0, fb0, fw1, fb1, fw2, fb2, out);
}

// round 5
// speedup vs baseline: 3.2458x; 1.5374x over previous
#include <cuda_runtime.h>

#define BB 8
#define NPTS 2048
#define KNN 20
#define NG 8
#define EPSV 1e-5f

#define NEG_INF __int_as_float(0xff800000)
#define POS_INF __int_as_float(0x7f800000)

// ---------------- device scratch ----------------
__device__ float g_pd[BB][NPTS][NPTS];
__device__ float g_xx[BB][NPTS];
__device__ int   g_knn[BB][NPTS][KNN];
__device__ float g_res[BB][NPTS][256];
__device__ float g_U[BB][NPTS][128];
__device__ float g_V[BB][NPTS][128];
__device__ float g_maxv[BB][NPTS][128];
__device__ float g_minv[BB][NPTS][128];
__device__ float g_z[BB][256][NPTS];
__device__ float g_ssum[BB * NG];
__device__ float g_ssq[BB * NG];
__device__ float g_pool[BB][512];

// ---------------- xx = sum_c f^2 (+ zero the stage stats) ----------------
__global__ void xx_kernel(const float* __restrict__ f, long long bs, int rs, int C) {
    if (blockIdx.x == 0 && threadIdx.x < BB * NG) {
        g_ssum[threadIdx.x] = 0.f; g_ssq[threadIdx.x] = 0.f;
    }
    int row = blockIdx.x * 8 + (threadIdx.x >> 5);
    int lane = threadIdx.x & 31;
    int b = row / NPTS, n = row % NPTS;
    const float* p = f + (long long)b * bs + (long long)n * rs;
    float s = 0.f;
    for (int c = lane; c < C; c += 32) { float v = p[c]; s += v * v; }
#pragma unroll
    for (int o = 16; o; o >>= 1) s += __shfl_xor_sync(0xffffffffu, s, o);
    if (lane == 0) g_xx[b][n] = s;
}

// ---------------- pd (C=3 path): 64x64 tile ----------------
template <int C>
__global__ void pd_kernel(const float* __restrict__ f, long long bs, int rs) {
    constexpr int KT = (C < 32) ? C : 32;
    __shared__ float sA[KT][68];
    __shared__ float sB[KT][68];
    int b = blockIdx.z;
    int n0 = blockIdx.y * 64, m0 = blockIdx.x * 64;
    int tx = threadIdx.x, ty = threadIdx.y;
    int tid = ty * 16 + tx;
    const float* fb = f + (long long)b * bs;
    float acc[4][4];
#pragma unroll
    for (int i = 0; i < 4; ++i)
#pragma unroll
        for (int j = 0; j < 4; ++j) acc[i][j] = 0.f;

    for (int k0 = 0; k0 < C; k0 += KT) {
        for (int t = tid; t < 64 * KT; t += 256) {
            int r = t / KT, c = t - r * KT;
            sA[c][r] = fb[(long long)(n0 + r) * rs + k0 + c];
            sB[c][r] = fb[(long long)(m0 + r) * rs + k0 + c];
        }
        __syncthreads();
#pragma unroll
        for (int c = 0; c < KT; ++c) {
            float4 a4 = *(const float4*)&sA[c][ty * 4];
            float4 b4 = *(const float4*)&sB[c][tx * 4];
            float a[4] = {a4.x, a4.y, a4.z, a4.w};
            float bv[4] = {b4.x, b4.y, b4.z, b4.w};
#pragma unroll
            for (int i = 0; i < 4; ++i)
#pragma unroll
                for (int j = 0; j < 4; ++j) acc[i][j] += a[i] * bv[j];
        }
        __syncthreads();
    }
    float xn[4], xm[4];
#pragma unroll
    for (int i = 0; i < 4; ++i) xn[i] = g_xx[b][n0 + ty * 4 + i];
#pragma unroll
    for (int j = 0; j < 4; ++j) xm[j] = g_xx[b][m0 + tx * 4 + j];
#pragma unroll
    for (int i = 0; i < 4; ++i) {
        float4 o4;
        o4.x = -(xn[i] - 2.f * acc[i][0] + xm[0]);
        o4.y = -(xn[i] - 2.f * acc[i][1] + xm[1]);
        o4.z = -(xn[i] - 2.f * acc[i][2] + xm[2]);
        o4.w = -(xn[i] - 2.f * acc[i][3] + xm[3]);
        __stcs((float4*)&g_pd[b][n0 + ty * 4 + i][m0 + tx * 4], o4);
    }
}

// ---------------- pd (C=64 path): 128x128 tile, 8x8 per thread ----------------
__global__ void __launch_bounds__(256) pd_kernel128(const float* __restrict__ f, long long bs, int rs) {
    __shared__ float sA[32][132];
    __shared__ float sB[32][132];
    int b = blockIdx.z;
    int n0 = blockIdx.y * 128, m0 = blockIdx.x * 128;
    int tx = threadIdx.x, ty = threadIdx.y;
    int tid = ty * 16 + tx;
    const float* fb = f + (long long)b * bs;
    float acc[8][8];
#pragma unroll
    for (int i = 0; i < 8; ++i)
#pragma unroll
        for (int j = 0; j < 8; ++j) acc[i][j] = 0.f;

    for (int k0 = 0; k0 < 64; k0 += 32) {
        for (int t = tid; t < 128 * 32; t += 256) {
            int r = t >> 5, c = t & 31;
            sA[c][r] = fb[(long long)(n0 + r) * rs + k0 + c];
            sB[c][r] = fb[(long long)(m0 + r) * rs + k0 + c];
        }
        __syncthreads();
#pragma unroll
        for (int c = 0; c < 32; ++c) {
            float4 a0 = *(const float4*)&sA[c][ty * 8];
            float4 a1 = *(const float4*)&sA[c][ty * 8 + 4];
            float4 b0 = *(const float4*)&sB[c][tx * 8];
            float4 b1 = *(const float4*)&sB[c][tx * 8 + 4];
            float a[8] = {a0.x, a0.y, a0.z, a0.w, a1.x, a1.y, a1.z, a1.w};
            float bv[8] = {b0.x, b0.y, b0.z, b0.w, b1.x, b1.y, b1.z, b1.w};
#pragma unroll
            for (int i = 0; i < 8; ++i)
#pragma unroll
                for (int j = 0; j < 8; ++j) acc[i][j] += a[i] * bv[j];
        }
        __syncthreads();
    }
    float xn[8], xm[8];
#pragma unroll
    for (int i = 0; i < 8; ++i) xn[i] = g_xx[b][n0 + ty * 8 + i];
#pragma unroll
    for (int j = 0; j < 8; ++j) xm[j] = g_xx[b][m0 + tx * 8 + j];
#pragma unroll
    for (int i = 0; i < 8; ++i) {
        int n = n0 + ty * 8 + i;
        float4 o4;
        o4.x = -(xn[i] - 2.f * acc[i][0] + xm[0]);
        o4.y = -(xn[i] - 2.f * acc[i][1] + xm[1]);
        o4.z = -(xn[i] - 2.f * acc[i][2] + xm[2]);
        o4.w = -(xn[i] - 2.f * acc[i][3] + xm[3]);
        __stcs((float4*)&g_pd[b][n][m0 + tx * 8], o4);
        o4.x = -(xn[i] - 2.f * acc[i][4] + xm[4]);
        o4.y = -(xn[i] - 2.f * acc[i][5] + xm[5]);
        o4.z = -(xn[i] - 2.f * acc[i][6] + xm[6]);
        o4.w = -(xn[i] - 2.f * acc[i][7] + xm[7]);
        __stcs((float4*)&g_pd[b][n][m0 + tx * 8 + 4], o4);
    }
}

// ---------------- exact top-K SET per row via radix-select (block per row) ----------------
__device__ __forceinline__ unsigned int fkey(float x) {
    unsigned int u = __float_as_uint(x);
    return (u & 0x80000000u) ? ~u : (u | 0x80000000u);
}

__global__ void __launch_bounds__(256) topk_kernel() {
    __shared__ unsigned int whist[8][256];   // per-warp histograms
    __shared__ unsigned int suff[256];
    __shared__ float candv[NPTS];
    __shared__ int   candi[NPTS];
    __shared__ int   s_cnt[2];               // [0]=cand count, [1]=definite count
    __shared__ int   s_binB, s_r;

    int row = blockIdx.x;
    int b = row >> 11, n = row & (NPTS - 1);
    int tid = threadIdx.x;
    int w = tid >> 5, lane = tid & 31;

#pragma unroll
    for (int i = 0; i < 8; ++i) whist[i][tid] = 0;
    if (tid < 2) s_cnt[tid] = 0;
    __syncthreads();

    // load 8 contiguous elements per thread, keep in registers
    const float4* pr4 = (const float4*)&g_pd[b][n][0];
    float4 x0 = __ldcs(&pr4[tid * 2]);
    float4 x1 = __ldcs(&pr4[tid * 2 + 1]);
    float xv[8] = {x0.x, x0.y, x0.z, x0.w, x1.x, x1.y, x1.z, x1.w};
    int bin[8];
#pragma unroll
    for (int q = 0; q < 8; ++q) {
        bin[q] = fkey(xv[q]) >> 24;
        atomicAdd(&whist[w][bin[q]], 1u);
    }
    __syncthreads();

    // total per-bin count + suffix scan (count of elements in bins > tid)
    unsigned int h = 0;
#pragma unroll
    for (int i = 0; i < 8; ++i) h += whist[i][tid];
    suff[tid] = h;
    __syncthreads();
#pragma unroll
    for (int off = 1; off < 256; off <<= 1) {
        unsigned int v = suff[tid] + ((tid + off < 256) ? suff[tid + off] : 0u);
        __syncthreads();
        suff[tid] = v;
        __syncthreads();
    }
    unsigned int cgt = suff[tid] - h;   // strictly-greater-bin count
    if (cgt < KNN && cgt + h >= KNN) { s_binB = tid; s_r = KNN - (int)cgt; }
    __syncthreads();
    int binB = s_binB, r = s_r;

    // scatter: definite members (bin > B) straight to output; bin==B to candidates
#pragma unroll
    for (int q = 0; q < 8; ++q) {
        int idx = tid * 8 + q;
        if (bin[q] > binB) {
            int p = atomicAdd(&s_cnt[1], 1);
            g_knn[b][n][p] = idx;
        } else if (bin[q] == binB) {
            int p = atomicAdd(&s_cnt[0], 1);
            candv[p] = xv[q]; candi[p] = idx;
        }
    }
    __syncthreads();

    // warp 0: extract top-r from candidates (value desc, index asc)
    if (w == 0) {
        int cnt = s_cnt[0];
        int base = s_cnt[1];   // == KNN - r
        for (int round = 0; round < r; ++round) {
            unsigned long long best = 0ull; int bp = -1;
            for (int p = lane; p < cnt; p += 32) {
                float v = candv[p];
                unsigned long long pk = ((unsigned long long)fkey(v) << 32)
                                      | (unsigned int)(0xffffffffu - (unsigned int)candi[p]);
                if (v != NEG_INF && pk > best) { best = pk; bp = p; }
            }
            unsigned long long wb = best;
#pragma unroll
            for (int o = 16; o; o >>= 1) {
                unsigned long long ov = __shfl_xor_sync(0xffffffffu, wb, o);
                if (ov > wb) wb = ov;
            }
            if (best == wb && bp >= 0) {
                candv[bp] = NEG_INF;
                g_knn[b][n][base + round] = (int)(0xffffffffu - (unsigned int)(wb & 0xffffffffu));
            }
            __syncwarp();
        }
    }
}

// ---------------- U = f*W1^T, V = f*(W2-W1)^T + b ----------------
template <int C>
__global__ void uv_gemm(const float* __restrict__ f, long long bs, int rs,
                        const float* __restrict__ w, const float* __restrict__ bias) {
    constexpr int KT = (C < 32) ? C : 32;
    __shared__ float sF[KT][68];
    __shared__ float sW1[KT][68];
    __shared__ float sDW[KT][68];
    int b = blockIdx.y;
    int n0 = blockIdx.x * 64;
    int o0 = blockIdx.z * 64;
    int tx = threadIdx.x, ty = threadIdx.y;
    int tid = ty * 16 + tx;
    const float* fb = f + (long long)b * bs;
    float au[4][4], av[4][4];
#pragma unroll
    for (int i = 0; i < 4; ++i)
#pragma unroll
        for (int j = 0; j < 4; ++j) { au[i][j] = 0.f; av[i][j] = 0.f; }

    for (int k0 = 0; k0 < C; k0 += KT) {
        for (int t = tid; t < 64 * KT; t += 256) {
            int r = t / KT, c = t - r * KT;
            sF[c][r] = fb[(long long)(n0 + r) * rs + k0 + c];
            float w1 = w[(o0 + r) * 2 * C + k0 + c];
            float w2 = w[(o0 + r) * 2 * C + C + k0 + c];
            sW1[c][r] = w1; sDW[c][r] = w2 - w1;
        }
        __syncthreads();
#pragma unroll
        for (int c = 0; c < KT; ++c) {
            float4 f4 = *(const float4*)&sF[c][ty * 4];
            float4 w4 = *(const float4*)&sW1[c][tx * 4];
            float4 d4 = *(const float4*)&sDW[c][tx * 4];
            float a[4] = {f4.x, f4.y, f4.z, f4.w};
            float wv[4] = {w4.x, w4.y, w4.z, w4.w};
            float dv[4] = {d4.x, d4.y, d4.z, d4.w};
#pragma unroll
            for (int i = 0; i < 4; ++i)
#pragma unroll
                for (int j = 0; j < 4; ++j) {
                    au[i][j] += a[i] * wv[j];
                    av[i][j] += a[i] * dv[j];
                }
        }
        __syncthreads();
    }
    float bb0 = bias[o0 + tx * 4 + 0];
    float bb1 = bias[o0 + tx * 4 + 1];
    float bb2 = bias[o0 + tx * 4 + 2];
    float bb3 = bias[o0 + tx * 4 + 3];
#pragma unroll
    for (int i = 0; i < 4; ++i) {
        int n = n0 + ty * 4 + i;
        float4 u4 = {au[i][0], au[i][1], au[i][2], au[i][3]};
        float4 v4 = {av[i][0] + bb0, av[i][1] + bb1, av[i][2] + bb2, av[i][3] + bb3};
        *(float4*)&g_U[b][n][o0 + tx * 4] = u4;
        *(float4*)&g_V[b][n][o0 + tx * 4] = v4;
    }
}

// ---------------- gather + k-max/min + GN stats ----------------
template <int O, int P>
__global__ void gather_reduce() {
    constexpr int PY = 256 / O;
    __shared__ int sidx[P][KNN];
    __shared__ float red[256];
    int o = threadIdx.x, py = threadIdx.y;
    int t = py * O + o;
    int b = blockIdx.y, n0 = blockIdx.x * P;
    for (int j = t; j < P * KNN; j += 256)
        sidx[j / KNN][j % KNN] = g_knn[b][n0 + j / KNN][j % KNN];
    __syncthreads();
    float ts1 = 0.f, ts2 = 0.f;
    for (int p = py; p < P; p += PY) {
        int n = n0 + p;
        float v = g_V[b][n][o];
        float mx = NEG_INF, mn = POS_INF;
#pragma unroll
        for (int k = 0; k < KNN; ++k) {
            float y = g_U[b][sidx[p][k]][o] + v;
            mx = fmaxf(mx, y); mn = fminf(mn, y);
            ts1 += y; ts2 += y * y;
        }
        g_maxv[b][n][o] = mx;
        g_minv[b][n][o] = mn;
    }
    red[t] = ts1; __syncthreads();
    if (t < NG) {
        float s = 0.f;
        for (int pp = 0; pp < PY; ++pp)
            for (int i = 0; i < O / NG; ++i) s += red[pp * O + t * (O / NG) + i];
        atomicAdd(&g_ssum[b * NG + t], s);
    }
    __syncthreads();
    red[t] = ts2; __syncthreads();
    if (t < NG) {
        float s = 0.f;
        for (int pp = 0; pp < PY; ++pp)
            for (int i = 0; i < O / NG; ++i) s += red[pp * O + t * (O / NG) + i];
        atomicAdd(&g_ssq[b * NG + t], s);
    }
}

// ---------------- GN + lrelu applied to k-extremum ----------------
template <int O>
__global__ void apply_kernel(const float* __restrict__ gamma, const float* __restrict__ beta, int col0) {
    int l = blockIdx.x * blockDim.x + threadIdx.x;
    int o = l % O;
    int n = (l / O) % NPTS;
    int b = l / (O * NPTS);
    int g = o / (O / NG);
    float cnt = (float)(O / NG) * NPTS * KNN;
    float mean = g_ssum[b * NG + g] / cnt;
    float var = fmaxf(g_ssq[b * NG + g] / cnt - mean * mean, 0.f);
    float inv = rsqrtf(var + EPSV);
    float s = gamma[o] * inv;
    float tt = beta[o] - mean * s;
    float sel = (s >= 0.f) ? g_maxv[b][n][o] : g_minv[b][n][o];
    float yv = s * sel + tt;
    g_res[b][n][col0 + o] = (yv >= 0.f) ? yv : 0.2f * yv;
}

// ---------------- w3 pointwise GEMM: 128x128 tile, 8x8 per thread ----------------
__global__ void __launch_bounds__(256) w3_gemm128(const float* __restrict__ w3, const float* __restrict__ b3) {
    __shared__ float sW[32][132];
    __shared__ float sR[32][132];
    int b = blockIdx.z;
    int o0 = blockIdx.y * 128, n0 = blockIdx.x * 128;
    int tx = threadIdx.x, ty = threadIdx.y;
    int tid = ty * 16 + tx;
    float acc[8][8];
#pragma unroll
    for (int i = 0; i < 8; ++i)
#pragma unroll
        for (int j = 0; j < 8; ++j) acc[i][j] = 0.f;

    for (int k0 = 0; k0 < 256; k0 += 32) {
        for (int t = tid; t < 128 * 32; t += 256) {
            int r = t >> 5, c = t & 31;
            sW[c][r] = w3[(o0 + r) * 256 + k0 + c];
            sR[c][r] = g_res[b][n0 + r][k0 + c];
        }
        __syncthreads();
#pragma unroll
        for (int c = 0; c < 32; ++c) {
            float4 a0 = *(const float4*)&sW[c][ty * 8];
            float4 a1 = *(const float4*)&sW[c][ty * 8 + 4];
            float4 b0 = *(const float4*)&sR[c][tx * 8];
            float4 b1 = *(const float4*)&sR[c][tx * 8 + 4];
            float a[8] = {a0.x, a0.y, a0.z, a0.w, a1.x, a1.y, a1.z, a1.w};
            float bv[8] = {b0.x, b0.y, b0.z, b0.w, b1.x, b1.y, b1.z, b1.w};
#pragma unroll
            for (int i = 0; i < 8; ++i)
#pragma unroll
                for (int j = 0; j < 8; ++j) acc[i][j] += a[i] * bv[j];
        }
        __syncthreads();
    }
#pragma unroll
    for (int i = 0; i < 8; ++i) {
        int o = o0 + ty * 8 + i;
        float bv = b3[o];
        float4 o4;
        o4.x = acc[i][0] + bv; o4.y = acc[i][1] + bv;
        o4.z = acc[i][2] + bv; o4.w = acc[i][3] + bv;
        *(float4*)&g_z[b][o][n0 + tx * 8] = o4;
        o4.x = acc[i][4] + bv; o4.y = acc[i][5] + bv;
        o4.z = acc[i][6] + bv; o4.w = acc[i][7] + bv;
        *(float4*)&g_z[b][o][n0 + tx * 8 + 4] = o4;
    }
}

// ---------------- stats of z per (b, group) ----------------
__global__ void stats3_kernel() {
    int b = blockIdx.x / NG, g = blockIdx.x % NG;
    int tid = threadIdx.x;
    float s1 = 0.f, s2 = 0.f;
    for (int i = tid; i < 32 * NPTS; i += 256) {
        int o = g * 32 + (i >> 11);
        int n = i & (NPTS - 1);
        float v = g_z[b][o][n];
        s1 += v; s2 += v * v;
    }
    __shared__ float r1[256], r2[256];
    r1[tid] = s1; r2[tid] = s2; __syncthreads();
    for (int st = 128; st; st >>= 1) {
        if (tid < st) { r1[tid] += r1[tid + st]; r2[tid] += r2[tid + st]; }
        __syncthreads();
    }
    if (tid == 0) { g_ssum[b * NG + g] = r1[0]; g_ssq[b * NG + g] = r2[0]; }
}

// ---------------- GN+lrelu+global max/mean pooling ----------------
__global__ void pool_kernel(const float* __restrict__ g3, const float* __restrict__ h3) {
    int b = blockIdx.x >> 8, o = blockIdx.x & 255;
    int g = o >> 5;
    float cnt = 32.f * NPTS;
    float mean = g_ssum[b * NG + g] / cnt;
    float var = fmaxf(g_ssq[b * NG + g] / cnt - mean * mean, 0.f);
    float inv = rsqrtf(var + EPSV);
    float s = g3[o] * inv;
    float tt = h3[o] - mean * s;
    int tid = threadIdx.x;
    float mx = NEG_INF, sum = 0.f;
    for (int n = tid; n < NPTS; n += 256) {
        float v = s * g_z[b][o][n] + tt;
        v = (v >= 0.f) ? v : 0.2f * v;
        mx = fmaxf(mx, v); sum += v;
    }
    __shared__ float rm[256], rs_[256];
    rm[tid] = mx; rs_[tid] = sum; __syncthreads();
    for (int st = 128; st; st >>= 1) {
        if (tid < st) { rm[tid] = fmaxf(rm[tid], rm[tid + st]); rs_[tid] += rs_[tid + st]; }
        __syncthreads();
    }
    if (tid == 0) { g_pool[b][o] = rm[0]; g_pool[b][256 + o] = rs_[0] / (float)NPTS; }
}

// ---------------- FC head ----------------
__global__ void head_kernel(const float* __restrict__ fw0, const float* __restrict__ fb0,
                            const float* __restrict__ fw1, const float* __restrict__ fb1,
                            const float* __restrict__ fw2, const float* __restrict__ fb2,
                            float* __restrict__ out) {
    __shared__ float sv[512];
    int b = blockIdx.x, t = threadIdx.x;
    sv[t] = g_pool[b][t];
    __syncthreads();
    float acc = fb0[t];
    {
        const float4* w4 = (const float4*)(fw0 + t * 512);
        const float4* v4 = (const float4*)sv;
        for (int c4 = 0; c4 < 128; ++c4) {
            float4 w = w4[c4]; float4 v = v4[c4];
            acc += w.x * v.x + w.y * v.y + w.z * v.z + w.w * v.w;
        }
    }
    acc = (acc >= 0.f) ? acc : 0.2f * acc;
    __syncthreads(); sv[t] = acc; __syncthreads();
    acc = fb1[t];
    {
        const float4* w4 = (const float4*)(fw1 + t * 512);
        const float4* v4 = (const float4*)sv;
        for (int c4 = 0; c4 < 128; ++c4) {
            float4 w = w4[c4]; float4 v = v4[c4];
            acc += w.x * v.x + w.y * v.y + w.z * v.z + w.w * v.w;
        }
    }
    acc = (acc >= 0.f) ? acc : 0.2f * acc;
    __syncthreads(); sv[t] = acc; __syncthreads();
    if (t < 256) {
        float a2 = fb2[t];
        const float4* w4 = (const float4*)(fw2 + t * 512);
        const float4* v4 = (const float4*)sv;
        for (int c4 = 0; c4 < 128; ++c4) {
            float4 w = w4[c4]; float4 v = v4[c4];
            a2 += w.x * v.x + w.y * v.y + w.z * v.z + w.w * v.w;
        }
        out[b * 256 + t] = a2;
    }
}

extern "C" void kernel_launch(void* const* d_in, const int* in_sizes, int n_in,
                              void* d_out, int out_size) {
    const float* x  = (const float*)d_in[0];
    const float* w0 = (const float*)d_in[1];
    const float* b0 = (const float*)d_in[2];
    const float* g0 = (const float*)d_in[3];
    const float* h0 = (const float*)d_in[4];
    const float* w1 = (const float*)d_in[5];
    const float* b1 = (const float*)d_in[6];
    const float* g1 = (const float*)d_in[7];
    const float* h1 = (const float*)d_in[8];
    const float* w2 = (const float*)d_in[9];
    const float* b2 = (const float*)d_in[10];
    const float* g2 = (const float*)d_in[11];
    const float* h2 = (const float*)d_in[12];
    const float* w3 = (const float*)d_in[13];
    const float* b3 = (const float*)d_in[14];
    const float* g3 = (const float*)d_in[15];
    const float* h3 = (const float*)d_in[16];
    const float* fw0 = (const float*)d_in[17];
    const float* fb0 = (const float*)d_in[18];
    const float* fw1 = (const float*)d_in[19];
    const float* fb1 = (const float*)d_in[20];
    const float* fw2 = (const float*)d_in[21];
    const float* fb2 = (const float*)d_in[22];
    float* out = (float*)d_out;

    float* resp = nullptr;
    cudaGetSymbolAddress((void**)&resp, g_res);

    dim3 blk16(16, 16);
    dim3 pd128grid(NPTS / 128, NPTS / 128, BB);

    // ---------- stage 1: C=3 -> O=64 ----------
    // order: xx(0), uv(1), pd(2), topk(3)  -> ncu captures launch index 3 = topk
    {
        long long bs = (long long)NPTS * 3;
        xx_kernel<<<BB * NPTS / 8, 256>>>(x, bs, 3, 3);
        uv_gemm<3><<<dim3(NPTS / 64, BB, 1), blk16>>>(x, bs, 3, w0, b0);
        pd_kernel<3><<<dim3(NPTS / 64, NPTS / 64, BB), blk16>>>(x, bs, 3);
        topk_kernel<<<BB * NPTS, 256>>>();
        gather_reduce<64, 16><<<dim3(NPTS / 16, BB), dim3(64, 4)>>>();
        apply_kernel<64><<<BB * NPTS * 64 / 256, 256>>>(g0, h0, 0);
    }
    // ---------- stage 2 ----------
    {
        long long bs = (long long)NPTS * 256;
        xx_kernel<<<BB * NPTS / 8, 256>>>(resp, bs, 256, 64);
        uv_gemm<64><<<dim3(NPTS / 64, BB, 1), blk16>>>(resp, bs, 256, w1, b1);
        pd_kernel128<<<pd128grid, blk16>>>(resp, bs, 256);
        topk_kernel<<<BB * NPTS, 256>>>();
        gather_reduce<64, 16><<<dim3(NPTS / 16, BB), dim3(64, 4)>>>();
        apply_kernel<64><<<BB * NPTS * 64 / 256, 256>>>(g1, h1, 64);
    }
    // ---------- stage 3 ----------
    {
        long long bs = (long long)NPTS * 256;
        const float* f = resp + 64;
        xx_kernel<<<BB * NPTS / 8, 256>>>(f, bs, 256, 64);
        uv_gemm<64><<<dim3(NPTS / 64, BB, 2), blk16>>>(f, bs, 256, w2, b2);
        pd_kernel128<<<pd128grid, blk16>>>(f, bs, 256);
        topk_kernel<<<BB * NPTS, 256>>>();
        gather_reduce<128, 8><<<dim3(NPTS / 8, BB), dim3(128, 2)>>>();
        apply_kernel<128><<<BB * NPTS * 128 / 256, 256>>>(g2, h2, 128);
    }
    // ---------- w3 pointwise + GN + pool + head ----------
    w3_gemm128<<<dim3(NPTS / 128, 256 / 128, BB), blk16>>>(w3, b3);
    stats3_kernel<<<BB * NG, 256>>>();
    pool_kernel<<<BB * 256, 256>>>(g3, h3);
    head_kernel<<<BB, 512>>>(fw0, fb0, fw1, fb1, fw2, fb2, out);
}

// round 7
// speedup vs baseline: 3.3445x; 1.0304x over previous
#include <cuda_runtime.h>

#define BB 8
#define NPTS 2048
#define KNN 20
#define NG 8
#define EPSV 1e-5f

#define NEG_INF __int_as_float(0xff800000)
#define POS_INF __int_as_float(0x7f800000)

// ---------------- device scratch ----------------
__device__ float g_pd[BB][NPTS][NPTS];
__device__ float g_xx[BB][NPTS];
__device__ int   g_knn[BB][NPTS][KNN];
__device__ float g_res[BB][NPTS][256];
__device__ float g_U[BB][NPTS][128];
__device__ float g_V[BB][NPTS][128];
__device__ float g_maxv[BB][NPTS][128];
__device__ float g_minv[BB][NPTS][128];
__device__ float g_z[BB][256][NPTS];
__device__ float g_ssum[BB * NG];
__device__ float g_ssq[BB * NG];
__device__ float g_pool[BB][512];

// ---------------- xx = sum_c f^2 (+ zero the stage stats) ----------------
__global__ void xx_kernel(const float* __restrict__ f, long long bs, int rs, int C) {
    if (blockIdx.x == 0 && threadIdx.x < BB * NG) {
        g_ssum[threadIdx.x] = 0.f; g_ssq[threadIdx.x] = 0.f;
    }
    int row = blockIdx.x * 8 + (threadIdx.x >> 5);
    int lane = threadIdx.x & 31;
    int b = row / NPTS, n = row % NPTS;
    const float* p = f + (long long)b * bs + (long long)n * rs;
    float s = 0.f;
    for (int c = lane; c < C; c += 32) { float v = p[c]; s += v * v; }
#pragma unroll
    for (int o = 16; o; o >>= 1) s += __shfl_xor_sync(0xffffffffu, s, o);
    if (lane == 0) g_xx[b][n] = s;
}

// ---------------- pd (C=3 path): 64x64 tile ----------------
template <int C>
__global__ void pd_kernel(const float* __restrict__ f, long long bs, int rs) {
    constexpr int KT = (C < 32) ? C : 32;
    __shared__ float sA[KT][68];
    __shared__ float sB[KT][68];
    int b = blockIdx.z;
    int n0 = blockIdx.y * 64, m0 = blockIdx.x * 64;
    int tx = threadIdx.x, ty = threadIdx.y;
    int tid = ty * 16 + tx;
    const float* fb = f + (long long)b * bs;
    float acc[4][4];
#pragma unroll
    for (int i = 0; i < 4; ++i)
#pragma unroll
        for (int j = 0; j < 4; ++j) acc[i][j] = 0.f;

    for (int k0 = 0; k0 < C; k0 += KT) {
        for (int t = tid; t < 64 * KT; t += 256) {
            int r = t / KT, c = t - r * KT;
            sA[c][r] = fb[(long long)(n0 + r) * rs + k0 + c];
            sB[c][r] = fb[(long long)(m0 + r) * rs + k0 + c];
        }
        __syncthreads();
#pragma unroll
        for (int c = 0; c < KT; ++c) {
            float4 a4 = *(const float4*)&sA[c][ty * 4];
            float4 b4 = *(const float4*)&sB[c][tx * 4];
            float a[4] = {a4.x, a4.y, a4.z, a4.w};
            float bv[4] = {b4.x, b4.y, b4.z, b4.w};
#pragma unroll
            for (int i = 0; i < 4; ++i)
#pragma unroll
                for (int j = 0; j < 4; ++j) acc[i][j] += a[i] * bv[j];
        }
        __syncthreads();
    }
    float xn[4], xm[4];
#pragma unroll
    for (int i = 0; i < 4; ++i) xn[i] = g_xx[b][n0 + ty * 4 + i];
#pragma unroll
    for (int j = 0; j < 4; ++j) xm[j] = g_xx[b][m0 + tx * 4 + j];
#pragma unroll
    for (int i = 0; i < 4; ++i) {
        float4 o4;
        o4.x = -(xn[i] - 2.f * acc[i][0] + xm[0]);
        o4.y = -(xn[i] - 2.f * acc[i][1] + xm[1]);
        o4.z = -(xn[i] - 2.f * acc[i][2] + xm[2]);
        o4.w = -(xn[i] - 2.f * acc[i][3] + xm[3]);
        __stcs((float4*)&g_pd[b][n0 + ty * 4 + i][m0 + tx * 4], o4);
    }
}

// ---------------- pd (C=64 path): 128x128 tile, 8x8 per thread ----------------
__global__ void __launch_bounds__(256) pd_kernel128(const float* __restrict__ f, long long bs, int rs) {
    __shared__ float sA[32][132];
    __shared__ float sB[32][132];
    int b = blockIdx.z;
    int n0 = blockIdx.y * 128, m0 = blockIdx.x * 128;
    int tx = threadIdx.x, ty = threadIdx.y;
    int tid = ty * 16 + tx;
    const float* fb = f + (long long)b * bs;
    float acc[8][8];
#pragma unroll
    for (int i = 0; i < 8; ++i)
#pragma unroll
        for (int j = 0; j < 8; ++j) acc[i][j] = 0.f;

    for (int k0 = 0; k0 < 64; k0 += 32) {
        for (int t = tid; t < 128 * 32; t += 256) {
            int r = t >> 5, c = t & 31;
            sA[c][r] = fb[(long long)(n0 + r) * rs + k0 + c];
            sB[c][r] = fb[(long long)(m0 + r) * rs + k0 + c];
        }
        __syncthreads();
#pragma unroll
        for (int c = 0; c < 32; ++c) {
            float4 a0 = *(const float4*)&sA[c][ty * 8];
            float4 a1 = *(const float4*)&sA[c][ty * 8 + 4];
            float4 b0 = *(const float4*)&sB[c][tx * 8];
            float4 b1 = *(const float4*)&sB[c][tx * 8 + 4];
            float a[8] = {a0.x, a0.y, a0.z, a0.w, a1.x, a1.y, a1.z, a1.w};
            float bv[8] = {b0.x, b0.y, b0.z, b0.w, b1.x, b1.y, b1.z, b1.w};
#pragma unroll
            for (int i = 0; i < 8; ++i)
#pragma unroll
                for (int j = 0; j < 8; ++j) acc[i][j] += a[i] * bv[j];
        }
        __syncthreads();
    }
    float xn[8], xm[8];
#pragma unroll
    for (int i = 0; i < 8; ++i) xn[i] = g_xx[b][n0 + ty * 8 + i];
#pragma unroll
    for (int j = 0; j < 8; ++j) xm[j] = g_xx[b][m0 + tx * 8 + j];
#pragma unroll
    for (int i = 0; i < 8; ++i) {
        int n = n0 + ty * 8 + i;
        float4 o4;
        o4.x = -(xn[i] - 2.f * acc[i][0] + xm[0]);
        o4.y = -(xn[i] - 2.f * acc[i][1] + xm[1]);
        o4.z = -(xn[i] - 2.f * acc[i][2] + xm[2]);
        o4.w = -(xn[i] - 2.f * acc[i][3] + xm[3]);
        __stcs((float4*)&g_pd[b][n][m0 + tx * 8], o4);
        o4.x = -(xn[i] - 2.f * acc[i][4] + xm[4]);
        o4.y = -(xn[i] - 2.f * acc[i][5] + xm[5]);
        o4.z = -(xn[i] - 2.f * acc[i][6] + xm[6]);
        o4.w = -(xn[i] - 2.f * acc[i][7] + xm[7]);
        __stcs((float4*)&g_pd[b][n][m0 + tx * 8 + 4], o4);
    }
}

// ---------------- exact top-K SET per row via 2-pass radix-select (block per row) ----------------
__device__ __forceinline__ unsigned int fkey(float x) {
    unsigned int u = __float_as_uint(x);
    return (u & 0x80000000u) ? ~u : (u | 0x80000000u);
}

#define C2MAX 320

__global__ void __launch_bounds__(256) topk_kernel() {
    __shared__ unsigned int whist[8][256];   // per-warp histograms
    __shared__ unsigned int suff[256];
    __shared__ float candv[NPTS];
    __shared__ int   candi[NPTS];
    __shared__ float c2v[C2MAX];
    __shared__ int   c2i[C2MAX];
    __shared__ int   s_cand, s_out, s_c2;
    __shared__ int   s_bin, s_r, s_bcnt;

    int row = blockIdx.x;
    int b = row >> 11, n = row & (NPTS - 1);
    int tid = threadIdx.x;
    int w = tid >> 5, lane = tid & 31;

#pragma unroll
    for (int i = 0; i < 8; ++i) whist[i][tid] = 0;
    if (tid == 0) { s_cand = 0; s_out = 0; s_c2 = 0; }
    __syncthreads();

    // load 8 contiguous elements per thread, keep in registers
    const float4* pr4 = (const float4*)&g_pd[b][n][0];
    float4 x0 = __ldcs(&pr4[tid * 2]);
    float4 x1 = __ldcs(&pr4[tid * 2 + 1]);
    float xv[8] = {x0.x, x0.y, x0.z, x0.w, x1.x, x1.y, x1.z, x1.w};
    int bin[8];
#pragma unroll
    for (int q = 0; q < 8; ++q) {
        bin[q] = fkey(xv[q]) >> 24;
        atomicAdd(&whist[w][bin[q]], 1u);
    }
    __syncthreads();

    // pass-1 bin totals + suffix scan
    unsigned int h = 0;
#pragma unroll
    for (int i = 0; i < 8; ++i) h += whist[i][tid];
    suff[tid] = h;
    __syncthreads();
#pragma unroll
    for (int off = 1; off < 256; off <<= 1) {
        unsigned int v = suff[tid] + ((tid + off < 256) ? suff[tid + off] : 0u);
        __syncthreads();
        suff[tid] = v;
        __syncthreads();
    }
    unsigned int cgt = suff[tid] - h;
    if (cgt < KNN && cgt + h >= KNN) { s_bin = tid; s_r = KNN - (int)cgt; }
    __syncthreads();
    int binB = s_bin, r = s_r;

    // scatter: definite members straight to output; critical bin to candidates
#pragma unroll
    for (int q = 0; q < 8; ++q) {
        int idx = tid * 8 + q;
        if (bin[q] > binB) {
            int p = atomicAdd(&s_out, 1);
            g_knn[b][n][p] = idx;
        } else if (bin[q] == binB) {
            int p = atomicAdd(&s_cand, 1);
            candv[p] = xv[q]; candi[p] = idx;
        }
    }
    __syncthreads();
    int cnt = s_cand;

    float* fv = candv; int* fi = candi;
    int fcnt = cnt, fr = r;

    if (cnt > 48) {
        // ---- pass 2: refine on key bits [16,24) ----
#pragma unroll
        for (int i = 0; i < 8; ++i) whist[i][tid] = 0;
        __syncthreads();
        for (int p = tid; p < cnt; p += 256) {
            int b2 = (fkey(candv[p]) >> 16) & 0xff;
            atomicAdd(&whist[w][b2], 1u);
        }
        __syncthreads();
        unsigned int h2 = 0;
#pragma unroll
        for (int i = 0; i < 8; ++i) h2 += whist[i][tid];
        suff[tid] = h2;
        __syncthreads();
#pragma unroll
        for (int off = 1; off < 256; off <<= 1) {
            unsigned int v = suff[tid] + ((tid + off < 256) ? suff[tid + off] : 0u);
            __syncthreads();
            suff[tid] = v;
            __syncthreads();
        }
        unsigned int cgt2 = suff[tid] - h2;
        if (cgt2 < (unsigned)r && cgt2 + h2 >= (unsigned)r) {
            s_bin = tid; s_r = r - (int)cgt2; s_bcnt = (int)h2;
        }
        __syncthreads();
        int binB2 = s_bin, r2 = s_r, bcnt = s_bcnt;

        if (bcnt <= C2MAX) {   // safe to refine (always true in practice)
            for (int p = tid; p < cnt; p += 256) {
                int b2 = (fkey(candv[p]) >> 16) & 0xff;
                if (b2 > binB2) {
                    int q = atomicAdd(&s_out, 1);
                    g_knn[b][n][q] = candi[p];
                } else if (b2 == binB2) {
                    int q = atomicAdd(&s_c2, 1);
                    c2v[q] = candv[p]; c2i[q] = candi[p];
                }
            }
            __syncthreads();
            fv = c2v; fi = c2i; fcnt = s_c2; fr = r2;
        }
    }

    // warp 0: extract top-fr from the (small) candidate set (value desc, index asc)
    if (w == 0) {
        int base = s_out;   // == KNN - fr
        for (int round = 0; round < fr; ++round) {
            unsigned long long best = 0ull; int bp = -1;
            for (int p = lane; p < fcnt; p += 32) {
                float v = fv[p];
                unsigned long long pk = ((unsigned long long)fkey(v) << 32)
                                      | (unsigned int)(0xffffffffu - (unsigned int)fi[p]);
                if (v != NEG_INF && pk > best) { best = pk; bp = p; }
            }
            unsigned long long wb = best;
#pragma unroll
            for (int o = 16; o; o >>= 1) {
                unsigned long long ov = __shfl_xor_sync(0xffffffffu, wb, o);
                if (ov > wb) wb = ov;
            }
            if (best == wb && bp >= 0) {
                fv[bp] = NEG_INF;
                g_knn[b][n][base + round] = (int)(0xffffffffu - (unsigned int)(wb & 0xffffffffu));
            }
            __syncwarp();
        }
    }
}

// ---------------- U = f*W1^T, V = f*(W2-W1)^T + b ----------------
template <int C>
__global__ void uv_gemm(const float* __restrict__ f, long long bs, int rs,
                        const float* __restrict__ w, const float* __restrict__ bias) {
    constexpr int KT = (C < 32) ? C : 32;
    __shared__ float sF[KT][68];
    __shared__ float sW1[KT][68];
    __shared__ float sDW[KT][68];
    int b = blockIdx.y;
    int n0 = blockIdx.x * 64;
    int o0 = blockIdx.z * 64;
    int tx = threadIdx.x, ty = threadIdx.y;
    int tid = ty * 16 + tx;
    const float* fb = f + (long long)b * bs;
    float au[4][4], av[4][4];
#pragma unroll
    for (int i = 0; i < 4; ++i)
#pragma unroll
        for (int j = 0; j < 4; ++j) { au[i][j] = 0.f; av[i][j] = 0.f; }

    for (int k0 = 0; k0 < C; k0 += KT) {
        for (int t = tid; t < 64 * KT; t += 256) {
            int r = t / KT, c = t - r * KT;
            sF[c][r] = fb[(long long)(n0 + r) * rs + k0 + c];
            float w1 = w[(o0 + r) * 2 * C + k0 + c];
            float w2 = w[(o0 + r) * 2 * C + C + k0 + c];
            sW1[c][r] = w1; sDW[c][r] = w2 - w1;
        }
        __syncthreads();
#pragma unroll
        for (int c = 0; c < KT; ++c) {
            float4 f4 = *(const float4*)&sF[c][ty * 4];
            float4 w4 = *(const float4*)&sW1[c][tx * 4];
            float4 d4 = *(const float4*)&sDW[c][tx * 4];
            float a[4] = {f4.x, f4.y, f4.z, f4.w};
            float wv[4] = {w4.x, w4.y, w4.z, w4.w};
            float dv[4] = {d4.x, d4.y, d4.z, d4.w};
#pragma unroll
            for (int i = 0; i < 4; ++i)
#pragma unroll
                for (int j = 0; j < 4; ++j) {
                    au[i][j] += a[i] * wv[j];
                    av[i][j] += a[i] * dv[j];
                }
        }
        __syncthreads();
    }
    float bb0 = bias[o0 + tx * 4 + 0];
    float bb1 = bias[o0 + tx * 4 + 1];
    float bb2 = bias[o0 + tx * 4 + 2];
    float bb3 = bias[o0 + tx * 4 + 3];
#pragma unroll
    for (int i = 0; i < 4; ++i) {
        int n = n0 + ty * 4 + i;
        float4 u4 = {au[i][0], au[i][1], au[i][2], au[i][3]};
        float4 v4 = {av[i][0] + bb0, av[i][1] + bb1, av[i][2] + bb2, av[i][3] + bb3};
        *(float4*)&g_U[b][n][o0 + tx * 4] = u4;
        *(float4*)&g_V[b][n][o0 + tx * 4] = v4;
    }
}

// ---------------- gather + k-max/min + GN stats ----------------
template <int O, int P>
__global__ void gather_reduce() {
    constexpr int PY = 256 / O;
    __shared__ int sidx[P][KNN];
    __shared__ float red[256];
    int o = threadIdx.x, py = threadIdx.y;
    int t = py * O + o;
    int b = blockIdx.y, n0 = blockIdx.x * P;
    for (int j = t; j < P * KNN; j += 256)
        sidx[j / KNN][j % KNN] = g_knn[b][n0 + j / KNN][j % KNN];
    __syncthreads();
    float ts1 = 0.f, ts2 = 0.f;
    for (int p = py; p < P; p += PY) {
        int n = n0 + p;
        float v = g_V[b][n][o];
        float mx = NEG_INF, mn = POS_INF;
#pragma unroll
        for (int k = 0; k < KNN; ++k) {
            float y = g_U[b][sidx[p][k]][o] + v;
            mx = fmaxf(mx, y); mn = fminf(mn, y);
            ts1 += y; ts2 += y * y;
        }
        g_maxv[b][n][o] = mx;
        g_minv[b][n][o] = mn;
    }
    red[t] = ts1; __syncthreads();
    if (t < NG) {
        float s = 0.f;
        for (int pp = 0; pp < PY; ++pp)
            for (int i = 0; i < O / NG; ++i) s += red[pp * O + t * (O / NG) + i];
        atomicAdd(&g_ssum[b * NG + t], s);
    }
    __syncthreads();
    red[t] = ts2; __syncthreads();
    if (t < NG) {
        float s = 0.f;
        for (int pp = 0; pp < PY; ++pp)
            for (int i = 0; i < O / NG; ++i) s += red[pp * O + t * (O / NG) + i];
        atomicAdd(&g_ssq[b * NG + t], s);
    }
}

// ---------------- GN + lrelu applied to k-extremum ----------------
template <int O>
__global__ void apply_kernel(const float* __restrict__ gamma, const float* __restrict__ beta, int col0) {
    int l = blockIdx.x * blockDim.x + threadIdx.x;
    int o = l % O;
    int n = (l / O) % NPTS;
    int b = l / (O * NPTS);
    int g = o / (O / NG);
    float cnt = (float)(O / NG) * NPTS * KNN;
    float mean = g_ssum[b * NG + g] / cnt;
    float var = fmaxf(g_ssq[b * NG + g] / cnt - mean * mean, 0.f);
    float inv = rsqrtf(var + EPSV);
    float s = gamma[o] * inv;
    float tt = beta[o] - mean * s;
    float sel = (s >= 0.f) ? g_maxv[b][n][o] : g_minv[b][n][o];
    float yv = s * sel + tt;
    g_res[b][n][col0 + o] = (yv >= 0.f) ? yv : 0.2f * yv;
}

// ---------------- w3 pointwise GEMM: 128x128 tile, 8x8 per thread ----------------
__global__ void __launch_bounds__(256) w3_gemm128(const float* __restrict__ w3, const float* __restrict__ b3) {
    __shared__ float sW[32][132];
    __shared__ float sR[32][132];
    int b = blockIdx.z;
    int o0 = blockIdx.y * 128, n0 = blockIdx.x * 128;
    int tx = threadIdx.x, ty = threadIdx.y;
    int tid = ty * 16 + tx;
    float acc[8][8];
#pragma unroll
    for (int i = 0; i < 8; ++i)
#pragma unroll
        for (int j = 0; j < 8; ++j) acc[i][j] = 0.f;

    for (int k0 = 0; k0 < 256; k0 += 32) {
        for (int t = tid; t < 128 * 32; t += 256) {
            int r = t >> 5, c = t & 31;
            sW[c][r] = w3[(o0 + r) * 256 + k0 + c];
            sR[c][r] = g_res[b][n0 + r][k0 + c];
        }
        __syncthreads();
#pragma unroll
        for (int c = 0; c < 32; ++c) {
            float4 a0 = *(const float4*)&sW[c][ty * 8];
            float4 a1 = *(const float4*)&sW[c][ty * 8 + 4];
            float4 b0 = *(const float4*)&sR[c][tx * 8];
            float4 b1 = *(const float4*)&sR[c][tx * 8 + 4];
            float a[8] = {a0.x, a0.y, a0.z, a0.w, a1.x, a1.y, a1.z, a1.w};
            float bv[8] = {b0.x, b0.y, b0.z, b0.w, b1.x, b1.y, b1.z, b1.w};
#pragma unroll
            for (int i = 0; i < 8; ++i)
#pragma unroll
                for (int j = 0; j < 8; ++j) acc[i][j] += a[i] * bv[j];
        }
        __syncthreads();
    }
#pragma unroll
    for (int i = 0; i < 8; ++i) {
        int o = o0 + ty * 8 + i;
        float bv = b3[o];
        float4 o4;
        o4.x = acc[i][0] + bv; o4.y = acc[i][1] + bv;
        o4.z = acc[i][2] + bv; o4.w = acc[i][3] + bv;
        *(float4*)&g_z[b][o][n0 + tx * 8] = o4;
        o4.x = acc[i][4] + bv; o4.y = acc[i][5] + bv;
        o4.z = acc[i][6] + bv; o4.w = acc[i][7] + bv;
        *(float4*)&g_z[b][o][n0 + tx * 8 + 4] = o4;
    }
}

// ---------------- stats of z per (b, group) ----------------
__global__ void stats3_kernel() {
    int b = blockIdx.x / NG, g = blockIdx.x % NG;
    int tid = threadIdx.x;
    float s1 = 0.f, s2 = 0.f;
    for (int i = tid; i < 32 * NPTS; i += 256) {
        int o = g * 32 + (i >> 11);
        int n = i & (NPTS - 1);
        float v = g_z[b][o][n];
        s1 += v; s2 += v * v;
    }
    __shared__ float r1[256], r2[256];
    r1[tid] = s1; r2[tid] = s2; __syncthreads();
    for (int st = 128; st; st >>= 1) {
        if (tid < st) { r1[tid] += r1[tid + st]; r2[tid] += r2[tid + st]; }
        __syncthreads();
    }
    if (tid == 0) { g_ssum[b * NG + g] = r1[0]; g_ssq[b * NG + g] = r2[0]; }
}

// ---------------- GN+lrelu+global max/mean pooling ----------------
__global__ void pool_kernel(const float* __restrict__ g3, const float* __restrict__ h3) {
    int b = blockIdx.x >> 8, o = blockIdx.x & 255;
    int g = o >> 5;
    float cnt = 32.f * NPTS;
    float mean = g_ssum[b * NG + g] / cnt;
    float var = fmaxf(g_ssq[b * NG + g] / cnt - mean * mean, 0.f);
    float inv = rsqrtf(var + EPSV);
    float s = g3[o] * inv;
    float tt = h3[o] - mean * s;
    int tid = threadIdx.x;
    float mx = NEG_INF, sum = 0.f;
    for (int n = tid; n < NPTS; n += 256) {
        float v = s * g_z[b][o][n] + tt;
        v = (v >= 0.f) ? v : 0.2f * v;
        mx = fmaxf(mx, v); sum += v;
    }
    __shared__ float rm[256], rs_[256];
    rm[tid] = mx; rs_[tid] = sum; __syncthreads();
    for (int st = 128; st; st >>= 1) {
        if (tid < st) { rm[tid] = fmaxf(rm[tid], rm[tid + st]); rs_[tid] += rs_[tid + st]; }
        __syncthreads();
    }
    if (tid == 0) { g_pool[b][o] = rm[0]; g_pool[b][256 + o] = rs_[0] / (float)NPTS; }
}

// ---------------- FC head ----------------
__global__ void head_kernel(const float* __restrict__ fw0, const float* __restrict__ fb0,
                            const float* __restrict__ fw1, const float* __restrict__ fb1,
                            const float* __restrict__ fw2, const float* __restrict__ fb2,
                            float* __restrict__ out) {
    __shared__ float sv[512];
    int b = blockIdx.x, t = threadIdx.x;
    sv[t] = g_pool[b][t];
    __syncthreads();
    float acc = fb0[t];
    {
        const float4* w4 = (const float4*)(fw0 + t * 512);
        const float4* v4 = (const float4*)sv;
        for (int c4 = 0; c4 < 128; ++c4) {
            float4 w = w4[c4]; float4 v = v4[c4];
            acc += w.x * v.x + w.y * v.y + w.z * v.z + w.w * v.w;
        }
    }
    acc = (acc >= 0.f) ? acc : 0.2f * acc;
    __syncthreads(); sv[t] = acc; __syncthreads();
    acc = fb1[t];
    {
        const float4* w4 = (const float4*)(fw1 + t * 512);
        const float4* v4 = (const float4*)sv;
        for (int c4 = 0; c4 < 128; ++c4) {
            float4 w = w4[c4]; float4 v = v4[c4];
            acc += w.x * v.x + w.y * v.y + w.z * v.z + w.w * v.w;
        }
    }
    acc = (acc >= 0.f) ? acc : 0.2f * acc;
    __syncthreads(); sv[t] = acc; __syncthreads();
    if (t < 256) {
        float a2 = fb2[t];
        const float4* w4 = (const float4*)(fw2 + t * 512);
        const float4* v4 = (const float4*)sv;
        for (int c4 = 0; c4 < 128; ++c4) {
            float4 w = w4[c4]; float4 v = v4[c4];
            a2 += w.x * v.x + w.y * v.y + w.z * v.z + w.w * v.w;
        }
        out[b * 256 + t] = a2;
    }
}

extern "C" void kernel_launch(void* const* d_in, const int* in_sizes, int n_in,
                              void* d_out, int out_size) {
    const float* x  = (const float*)d_in[0];
    const float* w0 = (const float*)d_in[1];
    const float* b0 = (const float*)d_in[2];
    const float* g0 = (const float*)d_in[3];
    const float* h0 = (const float*)d_in[4];
    const float* w1 = (const float*)d_in[5];
    const float* b1 = (const float*)d_in[6];
    const float* g1 = (const float*)d_in[7];
    const float* h1 = (const float*)d_in[8];
    const float* w2 = (const float*)d_in[9];
    const float* b2 = (const float*)d_in[10];
    const float* g2 = (const float*)d_in[11];
    const float* h2 = (const float*)d_in[12];
    const float* w3 = (const float*)d_in[13];
    const float* b3 = (const float*)d_in[14];
    const float* g3 = (const float*)d_in[15];
    const float* h3 = (const float*)d_in[16];
    const float* fw0 = (const float*)d_in[17];
    const float* fb0 = (const float*)d_in[18];
    const float* fw1 = (const float*)d_in[19];
    const float* fb1 = (const float*)d_in[20];
    const float* fw2 = (const float*)d_in[21];
    const float* fb2 = (const float*)d_in[22];
    float* out = (float*)d_out;

    float* resp = nullptr;
    cudaGetSymbolAddress((void**)&resp, g_res);

    dim3 blk16(16, 16);
    dim3 pd128grid(NPTS / 128, NPTS / 128, BB);

    // ---------- stage 1: C=3 -> O=64 ----------
    // order: xx(0), uv(1), pd(2), topk(3)  -> ncu captures launch index 3 = topk
    {
        long long bs = (long long)NPTS * 3;
        xx_kernel<<<BB * NPTS / 8, 256>>>(x, bs, 3, 3);
        uv_gemm<3><<<dim3(NPTS / 64, BB, 1), blk16>>>(x, bs, 3, w0, b0);
        pd_kernel<3><<<dim3(NPTS / 64, NPTS / 64, BB), blk16>>>(x, bs, 3);
        topk_kernel<<<BB * NPTS, 256>>>();
        gather_reduce<64, 16><<<dim3(NPTS / 16, BB), dim3(64, 4)>>>();
        apply_kernel<64><<<BB * NPTS * 64 / 256, 256>>>(g0, h0, 0);
    }
    // ---------- stage 2 ----------
    {
        long long bs = (long long)NPTS * 256;
        xx_kernel<<<BB * NPTS / 8, 256>>>(resp, bs, 256, 64);
        uv_gemm<64><<<dim3(NPTS / 64, BB, 1), blk16>>>(resp, bs, 256, w1, b1);
        pd_kernel128<<<pd128grid, blk16>>>(resp, bs, 256);
        topk_kernel<<<BB * NPTS, 256>>>();
        gather_reduce<64, 16><<<dim3(NPTS / 16, BB), dim3(64, 4)>>>();
        apply_kernel<64><<<BB * NPTS * 64 / 256, 256>>>(g1, h1, 64);
    }
    // ---------- stage 3 ----------
    {
        long long bs = (long long)NPTS * 256;
        const float* f = resp + 64;
        xx_kernel<<<BB * NPTS / 8, 256>>>(f, bs, 256, 64);
        uv_gemm<64><<<dim3(NPTS / 64, BB, 2), blk16>>>(f, bs, 256, w2, b2);
        pd_kernel128<<<pd128grid, blk16>>>(f, bs, 256);
        topk_kernel<<<BB * NPTS, 256>>>();
        gather_reduce<128, 8><<<dim3(NPTS / 8, BB), dim3(128, 2)>>>();
        apply_kernel<128><<<BB * NPTS * 128 / 256, 256>>>(g2, h2, 128);
    }
    // ---------- w3 pointwise + GN + pool + head ----------
    w3_gemm128<<<dim3(NPTS / 128, 256 / 128, BB), blk16>>>(w3, b3);
    stats3_kernel<<<BB * NG, 256>>>();
    pool_kernel<<<BB * 256, 256>>>(g3, h3);
    head_kernel<<<BB, 512>>>(fw0, fb0, fw1, fb1, fw2, fb2, out);
}